// round 6
// baseline (speedup 1.0000x reference)
#include <cuda_runtime.h>
#include <cuda_bf16.h>
#include <cstdint>

// Problem constants (fixed by setup_inputs)
#define T_TOK   8192      // B*S = 4*2048
#define D_IN    2048
#define D_OUT   2048
#define R_RANK  64
#define N_EXP   16
#define N_COLS  80        // R + E combined small-GEMM width

// ---------------- device scratch (no allocations allowed) ----------------
__device__ float g_S[T_TOK * N_COLS];        // [token][0..63]=res_hidden, [64..79]=router logits
__device__ int   g_cnt[N_EXP];
__device__ int   g_tok[N_EXP * T_TOK];
__device__ float g_wt [N_EXP * T_TOK];
// int8 hi/lo quantized copies for the tensor-core base GEMM
__device__ int8_t g_x1[T_TOK * D_IN];
__device__ int8_t g_x2[T_TOK * D_IN];
__device__ int8_t g_w1[D_OUT * D_IN];
__device__ int8_t g_w2[D_OUT * D_IN];
__device__ float  g_sx[T_TOK];
__device__ float  g_sw[D_OUT];

// ---------------- helpers ----------------
__device__ __forceinline__ uint32_t smem_u32(const void* p) {
    uint32_t a;
    asm("{ .reg .u64 t; cvta.to.shared.u64 t, %1; cvt.u32.u64 %0, t; }" : "=r"(a) : "l"(p));
    return a;
}
__device__ __forceinline__ void cp16(uint32_t s, const void* g) {
    asm volatile("cp.async.cg.shared.global [%0], [%1], 16;" :: "r"(s), "l"(g) : "memory");
}
__device__ __forceinline__ void ldmatrix_x4(uint32_t* r, uint32_t addr) {
    asm volatile("ldmatrix.sync.aligned.m8n8.x4.shared.b16 {%0,%1,%2,%3}, [%4];"
                 : "=r"(r[0]), "=r"(r[1]), "=r"(r[2]), "=r"(r[3]) : "r"(addr));
}
__device__ __forceinline__ void imma16832(int* c, const uint32_t* a, uint32_t b0, uint32_t b1) {
    asm volatile(
        "mma.sync.aligned.m16n8k32.row.col.s32.s8.s8.s32 "
        "{%0,%1,%2,%3}, {%4,%5,%6,%7}, {%8,%9}, {%0,%1,%2,%3};"
        : "+r"(c[0]), "+r"(c[1]), "+r"(c[2]), "+r"(c[3])
        : "r"(a[0]), "r"(a[1]), "r"(a[2]), "r"(a[3]), "r"(b0), "r"(b1));
}
__device__ __forceinline__ void red_v4(float* p, float x, float y, float z, float w) {
    asm volatile("red.global.add.v4.f32 [%0], {%1,%2,%3,%4};"
                 :: "l"(p), "f"(x), "f"(y), "f"(z), "f"(w) : "memory");
}
#define CP_COMMIT() asm volatile("cp.async.commit_group;" ::: "memory")
#define CP_WAIT(n)  asm volatile("cp.async.wait_group %0;" :: "n"(n) : "memory")

// ============================================================================
// Kernel 0: per-row int8 hi/lo quantization.  src row -> q1 + q2/128, scale.
// One block (256 thr) per row of D_IN=2048 floats.
// ============================================================================
__global__ __launch_bounds__(256) void k0_quant(
    const float* __restrict__ src,
    int8_t* __restrict__ q1, int8_t* __restrict__ q2,
    float* __restrict__ scale)
{
    __shared__ float s_wmax[8];
    __shared__ float s_amax;

    const int row  = blockIdx.x;
    const int tid  = threadIdx.x;
    const int wid  = tid >> 5;
    const int lane = tid & 31;
    const float* r = src + (size_t)row * D_IN;

    float a[8];
    *(float4*)&a[0] = *(const float4*)&r[tid * 8];
    *(float4*)&a[4] = *(const float4*)&r[tid * 8 + 4];

    float m = 0.f;
#pragma unroll
    for (int j = 0; j < 8; j++) m = fmaxf(m, fabsf(a[j]));
#pragma unroll
    for (int off = 16; off > 0; off >>= 1)
        m = fmaxf(m, __shfl_xor_sync(0xFFFFFFFFu, m, off));
    if (lane == 0) s_wmax[wid] = m;
    __syncthreads();
    if (tid == 0) {
        float mm = s_wmax[0];
#pragma unroll
        for (int w = 1; w < 8; w++) mm = fmaxf(mm, s_wmax[w]);
        s_amax = mm;
    }
    __syncthreads();

    const float sx  = fmaxf(s_amax, 1e-20f) * (1.f / 127.f);
    const float inv = 1.f / sx;

    char c1[8], c2[8];
#pragma unroll
    for (int j = 0; j < 8; j++) {
        float f  = a[j] * inv;                    // |f| <= 127
        float x1 = rintf(f);
        x1 = fminf(fmaxf(x1, -127.f), 127.f);
        float x2 = rintf((f - x1) * 128.f);       // in [-64, 64]
        x2 = fminf(fmaxf(x2, -127.f), 127.f);
        c1[j] = (char)(int)x1;
        c2[j] = (char)(int)x2;
    }
    *(uint2*)&q1[(size_t)row * D_IN + tid * 8] = *(uint2*)c1;
    *(uint2*)&q2[(size_t)row * D_IN + tid * 8] = *(uint2*)c2;
    if (tid == 0) scale[row] = sx;
}

// ============================================================================
// Kernel 1: S = x @ [A^T | W_router^T]  (fp32 SIMT)
// ============================================================================
__global__ __launch_bounds__(256) void k1_small_gemm(
    const float* __restrict__ x,
    const float* __restrict__ A,
    const float* __restrict__ Wr)
{
    __shared__ float xs[128][68];
    __shared__ float ws[40][68];

    const int tid = threadIdx.x;
    if (blockIdx.x == 0 && blockIdx.y == 0 && tid < N_EXP) g_cnt[tid] = 0;

    const int m0 = blockIdx.y * 128;
    const int c0 = blockIdx.x * 40;
    const int tg = tid >> 3;
    const int cg = tid & 7;

    float acc[4][5];
#pragma unroll
    for (int i = 0; i < 4; i++)
#pragma unroll
        for (int j = 0; j < 5; j++) acc[i][j] = 0.f;

    for (int k0 = 0; k0 < D_IN; k0 += 64) {
#pragma unroll
        for (int it = 0; it < 8; it++) {
            int q = tid + it * 256;
            int row = q >> 4;
            int kc = (q & 15) << 2;
            float4 v = *(const float4*)&x[(size_t)(m0 + row) * D_IN + k0 + kc];
            *(float4*)&xs[row][kc] = v;
        }
        for (int q = tid; q < 40 * 16; q += 256) {
            int col = q >> 4;
            int kc = (q & 15) << 2;
            int gc = c0 + col;
            const float* src = (gc < R_RANK) ? (A + (size_t)gc * D_IN)
                                             : (Wr + (size_t)(gc - R_RANK) * D_IN);
            float4 v = *(const float4*)&src[k0 + kc];
            *(float4*)&ws[col][kc] = v;
        }
        __syncthreads();

#pragma unroll 16
        for (int kk = 0; kk < 64; kk++) {
            float av[4], bv[5];
#pragma unroll
            for (int i = 0; i < 4; i++) av[i] = xs[tg * 4 + i][kk];
#pragma unroll
            for (int j = 0; j < 5; j++) bv[j] = ws[cg * 5 + j][kk];
#pragma unroll
            for (int i = 0; i < 4; i++)
#pragma unroll
                for (int j = 0; j < 5; j++) acc[i][j] += av[i] * bv[j];
        }
        __syncthreads();
    }

#pragma unroll
    for (int i = 0; i < 4; i++) {
        size_t base = (size_t)(m0 + tg * 4 + i) * N_COLS + c0 + cg * 5;
#pragma unroll
        for (int j = 0; j < 5; j++) g_S[base + j] = acc[i][j];
    }
}

// ============================================================================
// Kernel 2: softmax + top-k + scatter
// ============================================================================
__global__ __launch_bounds__(128) void k2_router(const int* __restrict__ topk_ptr)
{
    int t = blockIdx.x * blockDim.x + threadIdx.x;
    if (t >= T_TOK) return;

    float p[N_EXP];
    float mx = -1e30f;
#pragma unroll
    for (int e = 0; e < N_EXP; e++) {
        p[e] = g_S[(size_t)t * N_COLS + R_RANK + e];
        mx = fmaxf(mx, p[e]);
    }
    float sum = 0.f;
#pragma unroll
    for (int e = 0; e < N_EXP; e++) { p[e] = __expf(p[e] - mx); sum += p[e]; }
    float inv = 1.f / sum;
#pragma unroll
    for (int e = 0; e < N_EXP; e++) p[e] *= inv;

    int k = topk_ptr ? *topk_ptr : 2;

    if (k > 0 && k < N_EXP) {
        unsigned sel = 0;
        float ssum = 0.f;
        for (int it = 0; it < k; it++) {
            int best = -1; float bv = -1.f;
#pragma unroll
            for (int e = 0; e < N_EXP; e++)
                if (!((sel >> e) & 1u) && p[e] > bv) { bv = p[e]; best = e; }
            sel |= 1u << best;
            ssum += bv;
        }
        float denom = 1.f / (ssum + 1e-6f);
#pragma unroll
        for (int e = 0; e < N_EXP; e++) {
            if ((sel >> e) & 1u) {
                float w = p[e] * denom;
                int slot = atomicAdd(&g_cnt[e], 1);
                g_tok[e * T_TOK + slot] = t;
                g_wt [e * T_TOK + slot] = w;
            }
        }
    } else {
#pragma unroll
        for (int e = 0; e < N_EXP; e++) {
            int slot = atomicAdd(&g_cnt[e], 1);
            g_tok[e * T_TOK + slot] = t;
            g_wt [e * T_TOK + slot] = p[e];
        }
    }
}

// ============================================================================
// Kernel 3: base GEMM via int8 mma (hi/lo, 3 MMAs per k32, 2 accumulators)
// CTA tile 128x64, BK=64 int8, 8 warps (2x4), warp tile 64x16, 3-stage cp.async.
// smem row stride 80B (64B data) -> conflict-free ldmatrix.
// ============================================================================
#define BK3       64
#define NCHUNK3   (D_IN / BK3)                 // 32
#define MAT_X     (128 * 80)                   // x1 / x2 tile bytes
#define MAT_W     (64 * 80)                    // w1 / w2 tile bytes
#define STAGE3    (2 * MAT_X + 2 * MAT_W)      // 30720
#define SMEM_K3   (3 * STAGE3)                 // 92160

__global__ __launch_bounds__(256, 2) void k3_imma_gemm(
    const float* __restrict__ bias, float* __restrict__ out)
{
    extern __shared__ char sm[];
    const int tid  = threadIdx.x;
    const int wid  = tid >> 5;
    const int lane = tid & 31;
    const int g    = lane >> 2;      // 0..7
    const int t4   = lane & 3;       // 0..3

    const int m0 = blockIdx.y * 128;
    const int n0 = blockIdx.x * 64;
    const int wm = (wid >> 2) * 64;  // warp M offset
    const int wn = (wid & 3) * 16;   // warp N offset

    const uint32_t sbase = smem_u32(sm);

    // ldmatrix lane address components (identical byte layout to bf16 k16)
    const int a_row = ((lane >> 3) & 1) * 8 + (lane & 7);
    const int a_kb  = (lane >> 4) * 16;
    const int b_row = ((lane >> 4) & 1) * 8 + (lane & 7);
    const int b_kb  = ((lane >> 3) & 1) * 16;

    int acc1[4][2][4], acc2[4][2][4];
#pragma unroll
    for (int mi = 0; mi < 4; mi++)
#pragma unroll
        for (int ni = 0; ni < 2; ni++)
#pragma unroll
            for (int r = 0; r < 4; r++) { acc1[mi][ni][r] = 0; acc2[mi][ni][r] = 0; }

    // ---- async load of one k-chunk (BK3=64 int8) into stage c%3 ----
    auto load_chunk = [&](int c) {
        const uint32_t stg = sbase + (c % 3) * STAGE3;
        const int k0 = c * BK3;
#pragma unroll
        for (int it = 0; it < 6; it++) {
            int q    = tid + it * 256;      // 0..1535
            int rq   = q >> 2;              // 0..383
            int quad = q & 3;
            if (rq < 256) {                 // x1 | x2
                int mat = rq >> 7;
                int row = rq & 127;
                const int8_t* src = mat ? g_x2 : g_x1;
                cp16(stg + mat * MAT_X + row * 80 + quad * 16,
                     &src[(size_t)(m0 + row) * D_IN + k0 + quad * 16]);
            } else {                        // w1 | w2
                int rw  = rq - 256;
                int mat = rw >> 6;
                int row = rw & 63;
                const int8_t* src = mat ? g_w2 : g_w1;
                cp16(stg + 2 * MAT_X + mat * MAT_W + row * 80 + quad * 16,
                     &src[(size_t)(n0 + row) * D_IN + k0 + quad * 16]);
            }
        }
        CP_COMMIT();
    };

    load_chunk(0);
    load_chunk(1);

    for (int c = 0; c < NCHUNK3; c++) {
        if (c + 2 < NCHUNK3) { load_chunk(c + 2); CP_WAIT(2); }
        else if (c + 1 < NCHUNK3) { CP_WAIT(1); }
        else { CP_WAIT(0); }
        __syncthreads();

        const uint32_t stg = sbase + (c % 3) * STAGE3;
        const uint32_t sX1 = stg;
        const uint32_t sX2 = stg + MAT_X;
        const uint32_t sW1 = stg + 2 * MAT_X;
        const uint32_t sW2 = stg + 2 * MAT_X + MAT_W;

#pragma unroll
        for (int ks = 0; ks < 2; ks++) {
            const uint32_t kso = ks * 32;   // 32 bytes per k-step (k32)

            uint32_t a1[4][4], a2[4][4];
#pragma unroll
            for (int mi = 0; mi < 4; mi++) {
                uint32_t aoff = (uint32_t)((wm + mi * 16 + a_row) * 80) + kso + a_kb;
                ldmatrix_x4(a1[mi], sX1 + aoff);
                ldmatrix_x4(a2[mi], sX2 + aoff);
            }
            // one x4 per matrix covers both n-tiles (wn..wn+7, wn+8..wn+15)
            uint32_t boff = (uint32_t)((wn + b_row) * 80) + kso + b_kb;
            uint32_t b1[4], b2[4];
            ldmatrix_x4(b1, sW1 + boff);
            ldmatrix_x4(b2, sW2 + boff);

#pragma unroll
            for (int ni = 0; ni < 2; ni++) {
#pragma unroll
                for (int mi = 0; mi < 4; mi++)
                    imma16832(acc1[mi][ni], a1[mi], b1[ni * 2], b1[ni * 2 + 1]);  // x1*w1
#pragma unroll
                for (int mi = 0; mi < 4; mi++)
                    imma16832(acc2[mi][ni], a1[mi], b2[ni * 2], b2[ni * 2 + 1]);  // x1*w2
#pragma unroll
                for (int mi = 0; mi < 4; mi++)
                    imma16832(acc2[mi][ni], a2[mi], b1[ni * 2], b1[ni * 2 + 1]);  // x2*w1
            }
        }
        __syncthreads();
    }

    // ---- epilogue: dequant + bias + store ----
    const float c128 = 1.f / 128.f;
#pragma unroll
    for (int mi = 0; mi < 4; mi++) {
        int row = m0 + wm + mi * 16 + g;
        float sx0 = g_sx[row];
        float sx1 = g_sx[row + 8];
#pragma unroll
        for (int ni = 0; ni < 2; ni++) {
            int col = n0 + wn + ni * 8 + t4 * 2;
            float2 swv = *(const float2*)&g_sw[col];
            float2 bv  = *(const float2*)&bias[col];
            float f0 = (float)acc1[mi][ni][0] + (float)acc2[mi][ni][0] * c128;
            float f1 = (float)acc1[mi][ni][1] + (float)acc2[mi][ni][1] * c128;
            float f2 = (float)acc1[mi][ni][2] + (float)acc2[mi][ni][2] * c128;
            float f3 = (float)acc1[mi][ni][3] + (float)acc2[mi][ni][3] * c128;
            float2 o0, o1;
            o0.x = f0 * sx0 * swv.x + bv.x;
            o0.y = f1 * sx0 * swv.y + bv.y;
            o1.x = f2 * sx1 * swv.x + bv.x;
            o1.y = f3 * sx1 * swv.y + bv.y;
            *(float2*)&out[(size_t)row * D_OUT + col]       = o0;
            *(float2*)&out[(size_t)(row + 8) * D_OUT + col] = o1;
        }
    }
}

// ============================================================================
// Kernel 4: delta — expert-grouped, block = (expert, 64-token tile), d-loop
// inside (H loaded once). 4 tok x 8 d microtile. red.v4 accumulation.
// ============================================================================
#define HS_STRIDE  68
#define BS_STRIDE  132
#define K4_SMEM    (64 * HS_STRIDE * 4 + 64 * BS_STRIDE * 4 + 64 * 4)  // 51968

__global__ __launch_bounds__(256) void k4_delta(
    const float* __restrict__ Bm,
    float* __restrict__ out)
{
    extern __shared__ float sm4[];
    float* Hs  = sm4;                          // [64][HS_STRIDE]  (r-major, w-scaled)
    float* Bsh = sm4 + 64 * HS_STRIDE;         // [64][BS_STRIDE]  (r-major)
    int*   stok = (int*)(sm4 + 64 * HS_STRIDE + 64 * BS_STRIDE);

    const int e     = blockIdx.x >> 5;         // 16 experts
    const int stile = blockIdx.x & 31;         // 32 token tiles
    const int cnt   = g_cnt[e];
    const int tid   = threadIdx.x;

    if (stile * 64 >= cnt) return;

    const int a = tid >> 4;    // 0..15 token group (4 tokens)
    const int b = tid & 15;    // 0..15 d group (8 d)

    for (int s0 = stile * 64; s0 < cnt; s0 += 32 * 64) {
        // ---- load H tile (64 slots x 64 r), transpose, scale by weight ----
#pragma unroll
        for (int it = 0; it < 4; it++) {
            int q    = tid + it * 256;
            int slot = q >> 4;
            int r4   = (q & 15) << 2;
            int s    = s0 + slot;
            float4 v = make_float4(0.f, 0.f, 0.f, 0.f);
            float  w = 0.f;
            int    t = -1;
            if (s < cnt) {
                t = g_tok[e * T_TOK + s];
                w = g_wt [e * T_TOK + s];
                v = *(const float4*)&g_S[(size_t)t * N_COLS + r4];
            }
            Hs[(r4 + 0) * HS_STRIDE + slot] = v.x * w;
            Hs[(r4 + 1) * HS_STRIDE + slot] = v.y * w;
            Hs[(r4 + 2) * HS_STRIDE + slot] = v.z * w;
            Hs[(r4 + 3) * HS_STRIDE + slot] = v.w * w;
            if (r4 == 0) stok[slot] = t;
        }
        __syncthreads();

        for (int d0 = 0; d0 < D_OUT; d0 += 128) {
            // ---- load B chunk (128 d x 64 r), transpose into [r][d] ----
#pragma unroll
            for (int it = 0; it < 8; it++) {
                int q  = tid + it * 256;
                int d  = q & 127;
                int r4 = (q >> 7) << 2;
                float4 v = *(const float4*)&Bm[((size_t)e * D_OUT + d0 + d) * R_RANK + r4];
                Bsh[(r4 + 0) * BS_STRIDE + d] = v.x;
                Bsh[(r4 + 1) * BS_STRIDE + d] = v.y;
                Bsh[(r4 + 2) * BS_STRIDE + d] = v.z;
                Bsh[(r4 + 3) * BS_STRIDE + d] = v.w;
            }
            __syncthreads();

            float acc[4][8];
#pragma unroll
            for (int i = 0; i < 4; i++)
#pragma unroll
                for (int j = 0; j < 8; j++) acc[i][j] = 0.f;

#pragma unroll
            for (int r = 0; r < 64; r++) {
                float4 av  = *(const float4*)&Hs[r * HS_STRIDE + a * 4];
                float4 bv0 = *(const float4*)&Bsh[r * BS_STRIDE + b * 8];
                float4 bv1 = *(const float4*)&Bsh[r * BS_STRIDE + b * 8 + 4];
                float aa[4] = {av.x, av.y, av.z, av.w};
                float bb[8] = {bv0.x, bv0.y, bv0.z, bv0.w, bv1.x, bv1.y, bv1.z, bv1.w};
#pragma unroll
                for (int i = 0; i < 4; i++)
#pragma unroll
                    for (int j = 0; j < 8; j++) acc[i][j] += aa[i] * bb[j];
            }

#pragma unroll
            for (int i = 0; i < 4; i++) {
                int t = stok[a * 4 + i];
                if (t < 0) continue;
                float* p = &out[(size_t)t * D_OUT + d0 + b * 8];
                red_v4(p,     acc[i][0], acc[i][1], acc[i][2], acc[i][3]);
                red_v4(p + 4, acc[i][4], acc[i][5], acc[i][6], acc[i][7]);
            }
            __syncthreads();
        }
        __syncthreads();
    }
}

// ============================================================================
// launch
// ============================================================================
extern "C" void kernel_launch(void* const* d_in, const int* in_sizes, int n_in,
                              void* d_out, int out_size)
{
    const float* x   = (const float*)d_in[0];
    const float* Wb  = (const float*)d_in[1];
    const float* bb  = (const float*)d_in[2];
    const float* A   = (const float*)d_in[3];
    const float* Bm  = (const float*)d_in[4];
    const float* Wr  = (const float*)d_in[5];
    const int* topk  = (n_in > 6) ? (const int*)d_in[6] : nullptr;
    float* out       = (float*)d_out;

    (void)in_sizes; (void)out_size;

    int8_t *p_x1, *p_x2, *p_w1, *p_w2;
    float  *p_sx, *p_sw;
    cudaGetSymbolAddress((void**)&p_x1, g_x1);
    cudaGetSymbolAddress((void**)&p_x2, g_x2);
    cudaGetSymbolAddress((void**)&p_w1, g_w1);
    cudaGetSymbolAddress((void**)&p_w2, g_w2);
    cudaGetSymbolAddress((void**)&p_sx, g_sx);
    cudaGetSymbolAddress((void**)&p_sw, g_sw);

    cudaFuncSetAttribute(k3_imma_gemm, cudaFuncAttributeMaxDynamicSharedMemorySize, SMEM_K3);
    cudaFuncSetAttribute(k4_delta,     cudaFuncAttributeMaxDynamicSharedMemorySize, K4_SMEM);

    k0_quant<<<T_TOK, 256>>>(x,  p_x1, p_x2, p_sx);
    k0_quant<<<D_OUT, 256>>>(Wb, p_w1, p_w2, p_sw);
    k1_small_gemm<<<dim3(2, T_TOK / 128), 256>>>(x, A, Wr);
    k2_router   <<<T_TOK / 128, 128>>>(topk);
    k3_imma_gemm<<<dim3(D_OUT / 64, T_TOK / 128), 256, SMEM_K3>>>(bb, out);
    k4_delta    <<<N_EXP * 32, 256, K4_SMEM>>>(Bm, out);
}

// round 7
// speedup vs baseline: 2.2144x; 2.2144x over previous
#include <cuda_runtime.h>
#include <cuda_fp16.h>
#include <cstdint>

// Problem constants (fixed by setup_inputs)
#define T_TOK   8192      // B*S = 4*2048
#define D_IN    2048
#define D_OUT   2048
#define R_RANK  64
#define N_EXP   16
#define N_COLS  80        // R + E combined small-GEMM width

// ---------------- device scratch (no allocations allowed) ----------------
__device__ float g_S[T_TOK * N_COLS];        // [token][0..63]=res_hidden, [64..79]=router logits
__device__ int   g_cnt[N_EXP];
__device__ int   g_tok[N_EXP * T_TOK];
__device__ float g_wt [N_EXP * T_TOK];
// fp16 hi/lo copies for the tensor-core base GEMM (2-term split)
__device__ __half g_xhi[T_TOK * D_IN];
__device__ __half g_xlo[T_TOK * D_IN];
__device__ __half g_whi[D_OUT * D_IN];

// ---------------- helpers ----------------
__device__ __forceinline__ uint32_t smem_u32(const void* p) {
    uint32_t a;
    asm("{ .reg .u64 t; cvta.to.shared.u64 t, %1; cvt.u32.u64 %0, t; }" : "=r"(a) : "l"(p));
    return a;
}
__device__ __forceinline__ void cp16(uint32_t s, const void* g) {
    asm volatile("cp.async.cg.shared.global [%0], [%1], 16;" :: "r"(s), "l"(g) : "memory");
}
__device__ __forceinline__ void ldmatrix_x4(uint32_t* r, uint32_t addr) {
    asm volatile("ldmatrix.sync.aligned.m8n8.x4.shared.b16 {%0,%1,%2,%3}, [%4];"
                 : "=r"(r[0]), "=r"(r[1]), "=r"(r[2]), "=r"(r[3]) : "r"(addr));
}
__device__ __forceinline__ void mma16816h(float* c, const uint32_t* a, uint32_t b0, uint32_t b1) {
    asm volatile(
        "mma.sync.aligned.m16n8k16.row.col.f32.f16.f16.f32 "
        "{%0,%1,%2,%3}, {%4,%5,%6,%7}, {%8,%9}, {%0,%1,%2,%3};"
        : "+f"(c[0]), "+f"(c[1]), "+f"(c[2]), "+f"(c[3])
        : "r"(a[0]), "r"(a[1]), "r"(a[2]), "r"(a[3]), "r"(b0), "r"(b1));
}
__device__ __forceinline__ void red_v4(float* p, float x, float y, float z, float w) {
    asm volatile("red.global.add.v4.f32 [%0], {%1,%2,%3,%4};"
                 :: "l"(p), "f"(x), "f"(y), "f"(z), "f"(w) : "memory");
}
#define CP_COMMIT() asm volatile("cp.async.commit_group;" ::: "memory")
#define CP_WAIT(n)  asm volatile("cp.async.wait_group %0;" :: "n"(n) : "memory")

// ============================================================================
// Kernel 0a: fp32 -> (hi, lo) fp16 split
// ============================================================================
__global__ __launch_bounds__(256) void k0_split_hl(
    const float* __restrict__ src, __half* __restrict__ hi,
    __half* __restrict__ lo, int n4)
{
    int i = blockIdx.x * blockDim.x + threadIdx.x;
    if (i >= n4) return;
    float4 v = *(const float4*)&src[(size_t)i * 4];
    __half h[4], l[4];
    float vv[4] = {v.x, v.y, v.z, v.w};
#pragma unroll
    for (int j = 0; j < 4; j++) {
        h[j] = __float2half_rn(vv[j]);
        l[j] = __float2half_rn(vv[j] - __half2float(h[j]));
    }
    *(uint2*)&hi[(size_t)i * 4] = *(uint2*)h;
    *(uint2*)&lo[(size_t)i * 4] = *(uint2*)l;
}

// Kernel 0b: fp32 -> fp16 (hi only, for W)
__global__ __launch_bounds__(256) void k0_split_h(
    const float* __restrict__ src, __half* __restrict__ hi, int n4)
{
    int i = blockIdx.x * blockDim.x + threadIdx.x;
    if (i >= n4) return;
    float4 v = *(const float4*)&src[(size_t)i * 4];
    __half h[4];
    h[0] = __float2half_rn(v.x); h[1] = __float2half_rn(v.y);
    h[2] = __float2half_rn(v.z); h[3] = __float2half_rn(v.w);
    *(uint2*)&hi[(size_t)i * 4] = *(uint2*)h;
}

// ============================================================================
// Kernel 1: S = x @ [A^T | W_router^T]  (fp32 SIMT)
// ============================================================================
__global__ __launch_bounds__(256) void k1_small_gemm(
    const float* __restrict__ x,
    const float* __restrict__ A,
    const float* __restrict__ Wr)
{
    __shared__ float xs[128][68];
    __shared__ float ws[40][68];

    const int tid = threadIdx.x;
    if (blockIdx.x == 0 && blockIdx.y == 0 && tid < N_EXP) g_cnt[tid] = 0;

    const int m0 = blockIdx.y * 128;
    const int c0 = blockIdx.x * 40;
    const int tg = tid >> 3;
    const int cg = tid & 7;

    float acc[4][5];
#pragma unroll
    for (int i = 0; i < 4; i++)
#pragma unroll
        for (int j = 0; j < 5; j++) acc[i][j] = 0.f;

    for (int k0 = 0; k0 < D_IN; k0 += 64) {
#pragma unroll
        for (int it = 0; it < 8; it++) {
            int q = tid + it * 256;
            int row = q >> 4;
            int kc = (q & 15) << 2;
            float4 v = *(const float4*)&x[(size_t)(m0 + row) * D_IN + k0 + kc];
            *(float4*)&xs[row][kc] = v;
        }
        for (int q = tid; q < 40 * 16; q += 256) {
            int col = q >> 4;
            int kc = (q & 15) << 2;
            int gc = c0 + col;
            const float* src = (gc < R_RANK) ? (A + (size_t)gc * D_IN)
                                             : (Wr + (size_t)(gc - R_RANK) * D_IN);
            float4 v = *(const float4*)&src[k0 + kc];
            *(float4*)&ws[col][kc] = v;
        }
        __syncthreads();

#pragma unroll 16
        for (int kk = 0; kk < 64; kk++) {
            float av[4], bv[5];
#pragma unroll
            for (int i = 0; i < 4; i++) av[i] = xs[tg * 4 + i][kk];
#pragma unroll
            for (int j = 0; j < 5; j++) bv[j] = ws[cg * 5 + j][kk];
#pragma unroll
            for (int i = 0; i < 4; i++)
#pragma unroll
                for (int j = 0; j < 5; j++) acc[i][j] += av[i] * bv[j];
        }
        __syncthreads();
    }

#pragma unroll
    for (int i = 0; i < 4; i++) {
        size_t base = (size_t)(m0 + tg * 4 + i) * N_COLS + c0 + cg * 5;
#pragma unroll
        for (int j = 0; j < 5; j++) g_S[base + j] = acc[i][j];
    }
}

// ============================================================================
// Kernel 2: softmax + top-k + scatter
// ============================================================================
__global__ __launch_bounds__(128) void k2_router(const int* __restrict__ topk_ptr)
{
    int t = blockIdx.x * blockDim.x + threadIdx.x;
    if (t >= T_TOK) return;

    float p[N_EXP];
    float mx = -1e30f;
#pragma unroll
    for (int e = 0; e < N_EXP; e++) {
        p[e] = g_S[(size_t)t * N_COLS + R_RANK + e];
        mx = fmaxf(mx, p[e]);
    }
    float sum = 0.f;
#pragma unroll
    for (int e = 0; e < N_EXP; e++) { p[e] = __expf(p[e] - mx); sum += p[e]; }
    float inv = 1.f / sum;
#pragma unroll
    for (int e = 0; e < N_EXP; e++) p[e] *= inv;

    int k = topk_ptr ? *topk_ptr : 2;

    if (k > 0 && k < N_EXP) {
        unsigned sel = 0;
        float ssum = 0.f;
        for (int it = 0; it < k; it++) {
            int best = -1; float bv = -1.f;
#pragma unroll
            for (int e = 0; e < N_EXP; e++)
                if (!((sel >> e) & 1u) && p[e] > bv) { bv = p[e]; best = e; }
            sel |= 1u << best;
            ssum += bv;
        }
        float denom = 1.f / (ssum + 1e-6f);
#pragma unroll
        for (int e = 0; e < N_EXP; e++) {
            if ((sel >> e) & 1u) {
                float w = p[e] * denom;
                int slot = atomicAdd(&g_cnt[e], 1);
                g_tok[e * T_TOK + slot] = t;
                g_wt [e * T_TOK + slot] = w;
            }
        }
    } else {
#pragma unroll
        for (int e = 0; e < N_EXP; e++) {
            int slot = atomicAdd(&g_cnt[e], 1);
            g_tok[e * T_TOK + slot] = t;
            g_wt [e * T_TOK + slot] = p[e];
        }
    }
}

// ============================================================================
// Kernel 3: base GEMM via mma.sync fp16 2-term split: out = (xh + xl) @ wh^T
// CTA tile 128x128, BK=32, 8 warps (2x4), warp tile 64x32, 2-stage cp.async.
// ldmatrix.x4 fragment loads; smem row stride 80B -> conflict-free.
// ============================================================================
#define BK       32
#define NCHUNK   (D_IN / BK)                 // 64
#define MAT_BYTES (128 * 80)                 // 10240
#define STAGE_BYTES (3 * MAT_BYTES)          // 30720 (Ah | Al | Bh)
#define SMEM_DYN (2 * STAGE_BYTES)           // 61440

__global__ __launch_bounds__(256, 2) void k3_mma_gemm(
    const float* __restrict__ bias, float* __restrict__ out)
{
    extern __shared__ char sm[];
    const int tid  = threadIdx.x;
    const int wid  = tid >> 5;
    const int lane = tid & 31;
    const int g    = lane >> 2;      // group id 0..7
    const int t4   = lane & 3;       // thread-in-group 0..3

    const int m0 = blockIdx.y * 128;
    const int n0 = blockIdx.x * 128;
    const int wm = (wid >> 2) * 64;  // warp M offset within CTA
    const int wn = (wid & 3) * 32;   // warp N offset within CTA

    const uint32_t sbase = smem_u32(sm);

    // ldmatrix per-lane address components
    const int a_row = ((lane >> 3) & 1) * 8 + (lane & 7);
    const int a_kb  = (lane >> 4) * 16;
    const int b_row = ((lane >> 4) & 1) * 8 + (lane & 7);
    const int b_kb  = ((lane >> 3) & 1) * 16;

    float acc[4][4][4];
#pragma unroll
    for (int mi = 0; mi < 4; mi++)
#pragma unroll
        for (int ni = 0; ni < 4; ni++)
#pragma unroll
            for (int r = 0; r < 4; r++) acc[mi][ni][r] = 0.f;

    // ---- async load of one k-chunk (Ah, Al, Bh) into stage p ----
    auto load_chunk = [&](int c) {
        const int p  = c & 1;
        const int k0 = c * BK;
#pragma unroll
        for (int it = 0; it < 6; it++) {
            int q    = tid + it * 256;          // 0..1535
            int mat  = q >> 9;                  // 0: Ahi, 1: Alo, 2: Bhi
            int row  = (q >> 2) & 127;
            int quad = q & 3;
            const __half* src = (mat == 0) ? g_xhi : (mat == 1) ? g_xlo : g_whi;
            int grow = ((mat < 2) ? m0 : n0) + row;
            uint32_t saddr = sbase + p * STAGE_BYTES + mat * MAT_BYTES
                           + row * 80 + quad * 16;
            cp16(saddr, &src[(size_t)grow * D_IN + k0 + quad * 8]);
        }
        CP_COMMIT();
    };

    load_chunk(0);

    for (int c = 0; c < NCHUNK; c++) {
        if (c + 1 < NCHUNK) { load_chunk(c + 1); CP_WAIT(1); }
        else { CP_WAIT(0); }
        __syncthreads();

        const uint32_t stg = sbase + (c & 1) * STAGE_BYTES;
        const uint32_t sAh = stg;
        const uint32_t sAl = stg + MAT_BYTES;
        const uint32_t sBh = stg + 2 * MAT_BYTES;

#pragma unroll
        for (int ks = 0; ks < 2; ks++) {
            const uint32_t kso = ks * 32;

            uint32_t aH[4][4], aL[4][4];
#pragma unroll
            for (int mi = 0; mi < 4; mi++) {
                uint32_t aoff = (uint32_t)((wm + mi * 16 + a_row) * 80) + kso + a_kb;
                ldmatrix_x4(aH[mi], sAh + aoff);
                ldmatrix_x4(aL[mi], sAl + aoff);
            }
            uint32_t bH[4][2];
#pragma unroll
            for (int nj = 0; nj < 2; nj++) {
                uint32_t boff = (uint32_t)((wn + nj * 16 + b_row) * 80) + kso + b_kb;
                uint32_t th[4];
                ldmatrix_x4(th, sBh + boff);
                bH[nj * 2][0] = th[0]; bH[nj * 2][1] = th[1];
                bH[nj * 2 + 1][0] = th[2]; bH[nj * 2 + 1][1] = th[3];
            }

            // 2-term accumulation; mi innermost -> independent accumulators.
#pragma unroll
            for (int ni = 0; ni < 4; ni++) {
#pragma unroll
                for (int mi = 0; mi < 4; mi++)
                    mma16816h(acc[mi][ni], aH[mi], bH[ni][0], bH[ni][1]);   // xh*wh
#pragma unroll
                for (int mi = 0; mi < 4; mi++)
                    mma16816h(acc[mi][ni], aL[mi], bH[ni][0], bH[ni][1]);   // xl*wh
            }
        }
        __syncthreads();
    }

    // ---- epilogue: bias add + store ----
#pragma unroll
    for (int mi = 0; mi < 4; mi++) {
        int row = m0 + wm + mi * 16 + g;
#pragma unroll
        for (int ni = 0; ni < 4; ni++) {
            int col = n0 + wn + ni * 8 + t4 * 2;
            float2 bv = *(const float2*)&bias[col];
            float2 o0, o1;
            o0.x = acc[mi][ni][0] + bv.x;
            o0.y = acc[mi][ni][1] + bv.y;
            o1.x = acc[mi][ni][2] + bv.x;
            o1.y = acc[mi][ni][3] + bv.y;
            *(float2*)&out[(size_t)row * D_OUT + col]       = o0;
            *(float2*)&out[(size_t)(row + 8) * D_OUT + col] = o1;
        }
    }
}

// ============================================================================
// Kernel 4: delta — expert-grouped, block = (expert, 64-token tile), d-loop
// inside (H loaded once). 4 tok x 8 d microtile. red.v4 accumulation.
// ============================================================================
#define HS_STRIDE  68
#define BS_STRIDE  132
#define K4_SMEM    (64 * HS_STRIDE * 4 + 64 * BS_STRIDE * 4 + 64 * 4)  // 51968

__global__ __launch_bounds__(256) void k4_delta(
    const float* __restrict__ Bm,
    float* __restrict__ out)
{
    extern __shared__ float sm4[];
    float* Hs  = sm4;                          // [64][HS_STRIDE]  (r-major, w-scaled)
    float* Bsh = sm4 + 64 * HS_STRIDE;         // [64][BS_STRIDE]  (r-major)
    int*   stok = (int*)(sm4 + 64 * HS_STRIDE + 64 * BS_STRIDE);

    const int e     = blockIdx.x >> 5;         // 16 experts
    const int stile = blockIdx.x & 31;         // 32 token tiles
    const int cnt   = g_cnt[e];
    const int tid   = threadIdx.x;

    if (stile * 64 >= cnt) return;

    const int a = tid >> 4;    // 0..15 token group (4 tokens)
    const int b = tid & 15;    // 0..15 d group (8 d)

    for (int s0 = stile * 64; s0 < cnt; s0 += 32 * 64) {
        // ---- load H tile (64 slots x 64 r), transpose, scale by weight ----
#pragma unroll
        for (int it = 0; it < 4; it++) {
            int q    = tid + it * 256;
            int slot = q >> 4;
            int r4   = (q & 15) << 2;
            int s    = s0 + slot;
            float4 v = make_float4(0.f, 0.f, 0.f, 0.f);
            float  w = 0.f;
            int    t = -1;
            if (s < cnt) {
                t = g_tok[e * T_TOK + s];
                w = g_wt [e * T_TOK + s];
                v = *(const float4*)&g_S[(size_t)t * N_COLS + r4];
            }
            Hs[(r4 + 0) * HS_STRIDE + slot] = v.x * w;
            Hs[(r4 + 1) * HS_STRIDE + slot] = v.y * w;
            Hs[(r4 + 2) * HS_STRIDE + slot] = v.z * w;
            Hs[(r4 + 3) * HS_STRIDE + slot] = v.w * w;
            if (r4 == 0) stok[slot] = t;
        }
        __syncthreads();

        for (int d0 = 0; d0 < D_OUT; d0 += 128) {
            // ---- load B chunk (128 d x 64 r), transpose into [r][d] ----
#pragma unroll
            for (int it = 0; it < 8; it++) {
                int q  = tid + it * 256;
                int d  = q & 127;
                int r4 = (q >> 7) << 2;
                float4 v = *(const float4*)&Bm[((size_t)e * D_OUT + d0 + d) * R_RANK + r4];
                Bsh[(r4 + 0) * BS_STRIDE + d] = v.x;
                Bsh[(r4 + 1) * BS_STRIDE + d] = v.y;
                Bsh[(r4 + 2) * BS_STRIDE + d] = v.z;
                Bsh[(r4 + 3) * BS_STRIDE + d] = v.w;
            }
            __syncthreads();

            float acc[4][8];
#pragma unroll
            for (int i = 0; i < 4; i++)
#pragma unroll
                for (int j = 0; j < 8; j++) acc[i][j] = 0.f;

#pragma unroll
            for (int r = 0; r < 64; r++) {
                float4 av  = *(const float4*)&Hs[r * HS_STRIDE + a * 4];
                float4 bv0 = *(const float4*)&Bsh[r * BS_STRIDE + b * 8];
                float4 bv1 = *(const float4*)&Bsh[r * BS_STRIDE + b * 8 + 4];
                float aa[4] = {av.x, av.y, av.z, av.w};
                float bb[8] = {bv0.x, bv0.y, bv0.z, bv0.w, bv1.x, bv1.y, bv1.z, bv1.w};
#pragma unroll
                for (int i = 0; i < 4; i++)
#pragma unroll
                    for (int j = 0; j < 8; j++) acc[i][j] += aa[i] * bb[j];
            }

#pragma unroll
            for (int i = 0; i < 4; i++) {
                int t = stok[a * 4 + i];
                if (t < 0) continue;
                float* p = &out[(size_t)t * D_OUT + d0 + b * 8];
                red_v4(p,     acc[i][0], acc[i][1], acc[i][2], acc[i][3]);
                red_v4(p + 4, acc[i][4], acc[i][5], acc[i][6], acc[i][7]);
            }
            __syncthreads();
        }
        __syncthreads();
    }
}

// ============================================================================
// launch
// ============================================================================
extern "C" void kernel_launch(void* const* d_in, const int* in_sizes, int n_in,
                              void* d_out, int out_size)
{
    const float* x   = (const float*)d_in[0];
    const float* Wb  = (const float*)d_in[1];
    const float* bb  = (const float*)d_in[2];
    const float* A   = (const float*)d_in[3];
    const float* Bm  = (const float*)d_in[4];
    const float* Wr  = (const float*)d_in[5];
    const int* topk  = (n_in > 6) ? (const int*)d_in[6] : nullptr;
    float* out       = (float*)d_out;

    (void)in_sizes; (void)out_size;

    __half *p_xhi, *p_xlo, *p_whi;
    cudaGetSymbolAddress((void**)&p_xhi, g_xhi);
    cudaGetSymbolAddress((void**)&p_xlo, g_xlo);
    cudaGetSymbolAddress((void**)&p_whi, g_whi);

    cudaFuncSetAttribute(k3_mma_gemm, cudaFuncAttributeMaxDynamicSharedMemorySize, SMEM_DYN);
    cudaFuncSetAttribute(k4_delta,    cudaFuncAttributeMaxDynamicSharedMemorySize, K4_SMEM);

    int n4x = T_TOK * D_IN / 4, n4w = D_OUT * D_IN / 4;
    k0_split_hl<<<(n4x + 255) / 256, 256>>>(x,  p_xhi, p_xlo, n4x);
    k0_split_h <<<(n4w + 255) / 256, 256>>>(Wb, p_whi, n4w);
    k1_small_gemm<<<dim3(2, T_TOK / 128), 256>>>(x, A, Wr);
    k2_router   <<<T_TOK / 128, 128>>>(topk);
    k3_mma_gemm <<<dim3(D_OUT / 128, T_TOK / 128), 256, SMEM_DYN>>>(bb, out);
    k4_delta    <<<N_EXP * 32, 256, K4_SMEM>>>(Bm, out);
}

// round 8
// speedup vs baseline: 2.2724x; 1.0262x over previous
#include <cuda_runtime.h>
#include <cuda_fp16.h>
#include <cstdint>

// Problem constants (fixed by setup_inputs)
#define T_TOK   8192      // B*S = 4*2048
#define D_IN    2048
#define D_OUT   2048
#define R_RANK  64
#define N_EXP   16
#define N_COLS  80        // R + E combined small-GEMM width

// ---------------- device scratch (no allocations allowed) ----------------
__device__ float g_S[T_TOK * N_COLS];        // [token][0..63]=res_hidden, [64..79]=router logits
__device__ int   g_cnt[N_EXP];
__device__ int   g_tok[N_EXP * T_TOK];
__device__ float g_wt [N_EXP * T_TOK];
// fp16 hi/lo copies for the tensor-core base GEMM (2-term split)
__device__ __half g_xhi[T_TOK * D_IN];
__device__ __half g_xlo[T_TOK * D_IN];
__device__ __half g_whi[D_OUT * D_IN];

// ---------------- helpers ----------------
__device__ __forceinline__ uint32_t smem_u32(const void* p) {
    uint32_t a;
    asm("{ .reg .u64 t; cvta.to.shared.u64 t, %1; cvt.u32.u64 %0, t; }" : "=r"(a) : "l"(p));
    return a;
}
__device__ __forceinline__ void cp16(uint32_t s, const void* g) {
    asm volatile("cp.async.cg.shared.global [%0], [%1], 16;" :: "r"(s), "l"(g) : "memory");
}
__device__ __forceinline__ void ldmatrix_x4(uint32_t* r, uint32_t addr) {
    asm volatile("ldmatrix.sync.aligned.m8n8.x4.shared.b16 {%0,%1,%2,%3}, [%4];"
                 : "=r"(r[0]), "=r"(r[1]), "=r"(r[2]), "=r"(r[3]) : "r"(addr));
}
__device__ __forceinline__ void mma16816h(float* c, const uint32_t* a, uint32_t b0, uint32_t b1) {
    asm volatile(
        "mma.sync.aligned.m16n8k16.row.col.f32.f16.f16.f32 "
        "{%0,%1,%2,%3}, {%4,%5,%6,%7}, {%8,%9}, {%0,%1,%2,%3};"
        : "+f"(c[0]), "+f"(c[1]), "+f"(c[2]), "+f"(c[3])
        : "r"(a[0]), "r"(a[1]), "r"(a[2]), "r"(a[3]), "r"(b0), "r"(b1));
}
__device__ __forceinline__ void red_v4(float* p, float x, float y, float z, float w) {
    asm volatile("red.global.add.v4.f32 [%0], {%1,%2,%3,%4};"
                 :: "l"(p), "f"(x), "f"(y), "f"(z), "f"(w) : "memory");
}
#define CP_COMMIT() asm volatile("cp.async.commit_group;" ::: "memory")
#define CP_WAIT(n)  asm volatile("cp.async.wait_group %0;" :: "n"(n) : "memory")

// ============================================================================
// Kernel 0a: fp32 -> (hi, lo) fp16 split
// ============================================================================
__global__ __launch_bounds__(256) void k0_split_hl(
    const float* __restrict__ src, __half* __restrict__ hi,
    __half* __restrict__ lo, int n4)
{
    int i = blockIdx.x * blockDim.x + threadIdx.x;
    if (i >= n4) return;
    float4 v = *(const float4*)&src[(size_t)i * 4];
    __half h[4], l[4];
    float vv[4] = {v.x, v.y, v.z, v.w};
#pragma unroll
    for (int j = 0; j < 4; j++) {
        h[j] = __float2half_rn(vv[j]);
        l[j] = __float2half_rn(vv[j] - __half2float(h[j]));
    }
    *(uint2*)&hi[(size_t)i * 4] = *(uint2*)h;
    *(uint2*)&lo[(size_t)i * 4] = *(uint2*)l;
}

// Kernel 0b: fp32 -> fp16 (hi only, for W)
__global__ __launch_bounds__(256) void k0_split_h(
    const float* __restrict__ src, __half* __restrict__ hi, int n4)
{
    int i = blockIdx.x * blockDim.x + threadIdx.x;
    if (i >= n4) return;
    float4 v = *(const float4*)&src[(size_t)i * 4];
    __half h[4];
    h[0] = __float2half_rn(v.x); h[1] = __float2half_rn(v.y);
    h[2] = __float2half_rn(v.z); h[3] = __float2half_rn(v.w);
    *(uint2*)&hi[(size_t)i * 4] = *(uint2*)h;
}

// ============================================================================
// Kernel 1: S = x @ [A^T | W_router^T]  (fp32 SIMT)
// ============================================================================
__global__ __launch_bounds__(256) void k1_small_gemm(
    const float* __restrict__ x,
    const float* __restrict__ A,
    const float* __restrict__ Wr)
{
    __shared__ float xs[128][68];
    __shared__ float ws[40][68];

    const int tid = threadIdx.x;
    if (blockIdx.x == 0 && blockIdx.y == 0 && tid < N_EXP) g_cnt[tid] = 0;

    const int m0 = blockIdx.y * 128;
    const int c0 = blockIdx.x * 40;
    const int tg = tid >> 3;
    const int cg = tid & 7;

    float acc[4][5];
#pragma unroll
    for (int i = 0; i < 4; i++)
#pragma unroll
        for (int j = 0; j < 5; j++) acc[i][j] = 0.f;

    for (int k0 = 0; k0 < D_IN; k0 += 64) {
#pragma unroll
        for (int it = 0; it < 8; it++) {
            int q = tid + it * 256;
            int row = q >> 4;
            int kc = (q & 15) << 2;
            float4 v = *(const float4*)&x[(size_t)(m0 + row) * D_IN + k0 + kc];
            *(float4*)&xs[row][kc] = v;
        }
        for (int q = tid; q < 40 * 16; q += 256) {
            int col = q >> 4;
            int kc = (q & 15) << 2;
            int gc = c0 + col;
            const float* src = (gc < R_RANK) ? (A + (size_t)gc * D_IN)
                                             : (Wr + (size_t)(gc - R_RANK) * D_IN);
            float4 v = *(const float4*)&src[k0 + kc];
            *(float4*)&ws[col][kc] = v;
        }
        __syncthreads();

#pragma unroll 16
        for (int kk = 0; kk < 64; kk++) {
            float av[4], bv[5];
#pragma unroll
            for (int i = 0; i < 4; i++) av[i] = xs[tg * 4 + i][kk];
#pragma unroll
            for (int j = 0; j < 5; j++) bv[j] = ws[cg * 5 + j][kk];
#pragma unroll
            for (int i = 0; i < 4; i++)
#pragma unroll
                for (int j = 0; j < 5; j++) acc[i][j] += av[i] * bv[j];
        }
        __syncthreads();
    }

#pragma unroll
    for (int i = 0; i < 4; i++) {
        size_t base = (size_t)(m0 + tg * 4 + i) * N_COLS + c0 + cg * 5;
#pragma unroll
        for (int j = 0; j < 5; j++) g_S[base + j] = acc[i][j];
    }
}

// ============================================================================
// Kernel 2: softmax + top-k + scatter
// ============================================================================
__global__ __launch_bounds__(128) void k2_router(const int* __restrict__ topk_ptr)
{
    int t = blockIdx.x * blockDim.x + threadIdx.x;
    if (t >= T_TOK) return;

    float p[N_EXP];
    float mx = -1e30f;
#pragma unroll
    for (int e = 0; e < N_EXP; e++) {
        p[e] = g_S[(size_t)t * N_COLS + R_RANK + e];
        mx = fmaxf(mx, p[e]);
    }
    float sum = 0.f;
#pragma unroll
    for (int e = 0; e < N_EXP; e++) { p[e] = __expf(p[e] - mx); sum += p[e]; }
    float inv = 1.f / sum;
#pragma unroll
    for (int e = 0; e < N_EXP; e++) p[e] *= inv;

    int k = topk_ptr ? *topk_ptr : 2;

    if (k > 0 && k < N_EXP) {
        unsigned sel = 0;
        float ssum = 0.f;
        for (int it = 0; it < k; it++) {
            int best = -1; float bv = -1.f;
#pragma unroll
            for (int e = 0; e < N_EXP; e++)
                if (!((sel >> e) & 1u) && p[e] > bv) { bv = p[e]; best = e; }
            sel |= 1u << best;
            ssum += bv;
        }
        float denom = 1.f / (ssum + 1e-6f);
#pragma unroll
        for (int e = 0; e < N_EXP; e++) {
            if ((sel >> e) & 1u) {
                float w = p[e] * denom;
                int slot = atomicAdd(&g_cnt[e], 1);
                g_tok[e * T_TOK + slot] = t;
                g_wt [e * T_TOK + slot] = w;
            }
        }
    } else {
#pragma unroll
        for (int e = 0; e < N_EXP; e++) {
            int slot = atomicAdd(&g_cnt[e], 1);
            g_tok[e * T_TOK + slot] = t;
            g_wt [e * T_TOK + slot] = p[e];
        }
    }
}

// ============================================================================
// Kernel 3: base GEMM via mma.sync fp16 2-term split: out = (xh + xl) @ wh^T
// CTA tile 128x128, BK=32, 8 warps (2x4), warp tile 64x32, 3-stage cp.async.
// ldmatrix.x4 fragment loads; smem row stride 80B -> conflict-free.
// ============================================================================
#define BK       32
#define NCHUNK   (D_IN / BK)                 // 64
#define MAT_BYTES (128 * 80)                 // 10240
#define STAGE_BYTES (3 * MAT_BYTES)          // 30720 (Ah | Al | Bh)
#define SMEM_DYN (3 * STAGE_BYTES)           // 92160

__global__ __launch_bounds__(256, 2) void k3_mma_gemm(
    const float* __restrict__ bias, float* __restrict__ out)
{
    extern __shared__ char sm[];
    const int tid  = threadIdx.x;
    const int wid  = tid >> 5;
    const int lane = tid & 31;
    const int g    = lane >> 2;      // group id 0..7
    const int t4   = lane & 3;       // thread-in-group 0..3

    const int m0 = blockIdx.y * 128;
    const int n0 = blockIdx.x * 128;
    const int wm = (wid >> 2) * 64;  // warp M offset within CTA
    const int wn = (wid & 3) * 32;   // warp N offset within CTA

    const uint32_t sbase = smem_u32(sm);

    // ldmatrix per-lane address components
    const int a_row = ((lane >> 3) & 1) * 8 + (lane & 7);
    const int a_kb  = (lane >> 4) * 16;
    const int b_row = ((lane >> 4) & 1) * 8 + (lane & 7);
    const int b_kb  = ((lane >> 3) & 1) * 16;

    float acc[4][4][4];
#pragma unroll
    for (int mi = 0; mi < 4; mi++)
#pragma unroll
        for (int ni = 0; ni < 4; ni++)
#pragma unroll
            for (int r = 0; r < 4; r++) acc[mi][ni][r] = 0.f;

    // ---- async load of one k-chunk (Ah, Al, Bh) into stage c%3 ----
    auto load_chunk = [&](int c) {
        const int p  = c % 3;
        const int k0 = c * BK;
#pragma unroll
        for (int it = 0; it < 6; it++) {
            int q    = tid + it * 256;          // 0..1535
            int mat  = q >> 9;                  // 0: Ahi, 1: Alo, 2: Bhi
            int row  = (q >> 2) & 127;
            int quad = q & 3;
            const __half* src = (mat == 0) ? g_xhi : (mat == 1) ? g_xlo : g_whi;
            int grow = ((mat < 2) ? m0 : n0) + row;
            uint32_t saddr = sbase + p * STAGE_BYTES + mat * MAT_BYTES
                           + row * 80 + quad * 16;
            cp16(saddr, &src[(size_t)grow * D_IN + k0 + quad * 8]);
        }
        CP_COMMIT();
    };

    load_chunk(0);
    load_chunk(1);

    for (int c = 0; c < NCHUNK; c++) {
        if (c + 2 < NCHUNK) { load_chunk(c + 2); CP_WAIT(2); }
        else if (c + 1 < NCHUNK) { CP_WAIT(1); }
        else { CP_WAIT(0); }
        __syncthreads();

        const uint32_t stg = sbase + (c % 3) * STAGE_BYTES;
        const uint32_t sAh = stg;
        const uint32_t sAl = stg + MAT_BYTES;
        const uint32_t sBh = stg + 2 * MAT_BYTES;

#pragma unroll
        for (int ks = 0; ks < 2; ks++) {
            const uint32_t kso = ks * 32;

            uint32_t aH[4][4], aL[4][4];
#pragma unroll
            for (int mi = 0; mi < 4; mi++) {
                uint32_t aoff = (uint32_t)((wm + mi * 16 + a_row) * 80) + kso + a_kb;
                ldmatrix_x4(aH[mi], sAh + aoff);
                ldmatrix_x4(aL[mi], sAl + aoff);
            }
            uint32_t bH[4][2];
#pragma unroll
            for (int nj = 0; nj < 2; nj++) {
                uint32_t boff = (uint32_t)((wn + nj * 16 + b_row) * 80) + kso + b_kb;
                uint32_t th[4];
                ldmatrix_x4(th, sBh + boff);
                bH[nj * 2][0] = th[0]; bH[nj * 2][1] = th[1];
                bH[nj * 2 + 1][0] = th[2]; bH[nj * 2 + 1][1] = th[3];
            }

            // 2-term accumulation; mi innermost -> independent accumulators.
#pragma unroll
            for (int ni = 0; ni < 4; ni++) {
#pragma unroll
                for (int mi = 0; mi < 4; mi++)
                    mma16816h(acc[mi][ni], aH[mi], bH[ni][0], bH[ni][1]);   // xh*wh
#pragma unroll
                for (int mi = 0; mi < 4; mi++)
                    mma16816h(acc[mi][ni], aL[mi], bH[ni][0], bH[ni][1]);   // xl*wh
            }
        }
        __syncthreads();
    }

    // ---- epilogue: bias add + store ----
#pragma unroll
    for (int mi = 0; mi < 4; mi++) {
        int row = m0 + wm + mi * 16 + g;
#pragma unroll
        for (int ni = 0; ni < 4; ni++) {
            int col = n0 + wn + ni * 8 + t4 * 2;
            float2 bv = *(const float2*)&bias[col];
            float2 o0, o1;
            o0.x = acc[mi][ni][0] + bv.x;
            o0.y = acc[mi][ni][1] + bv.y;
            o1.x = acc[mi][ni][2] + bv.x;
            o1.y = acc[mi][ni][3] + bv.y;
            *(float2*)&out[(size_t)row * D_OUT + col]       = o0;
            *(float2*)&out[(size_t)(row + 8) * D_OUT + col] = o1;
        }
    }
}

// ============================================================================
// Kernel 4: delta — expert-grouped, block = (expert, 64-token tile), d-loop
// inside (H loaded once). 4 tok x 8 d microtile. red.v4 accumulation.
// ============================================================================
#define HS_STRIDE  68
#define BS_STRIDE  132
#define K4_SMEM    (64 * HS_STRIDE * 4 + 64 * BS_STRIDE * 4 + 64 * 4)  // 51968

__global__ __launch_bounds__(256) void k4_delta(
    const float* __restrict__ Bm,
    float* __restrict__ out)
{
    extern __shared__ float sm4[];
    float* Hs  = sm4;                          // [64][HS_STRIDE]  (r-major, w-scaled)
    float* Bsh = sm4 + 64 * HS_STRIDE;         // [64][BS_STRIDE]  (r-major)
    int*   stok = (int*)(sm4 + 64 * HS_STRIDE + 64 * BS_STRIDE);

    const int e     = blockIdx.x >> 5;         // 16 experts
    const int stile = blockIdx.x & 31;         // 32 token tiles
    const int cnt   = g_cnt[e];
    const int tid   = threadIdx.x;

    if (stile * 64 >= cnt) return;

    const int a = tid >> 4;    // 0..15 token group (4 tokens)
    const int b = tid & 15;    // 0..15 d group (8 d)

    for (int s0 = stile * 64; s0 < cnt; s0 += 32 * 64) {
        // ---- load H tile (64 slots x 64 r), transpose, scale by weight ----
#pragma unroll
        for (int it = 0; it < 4; it++) {
            int q    = tid + it * 256;
            int slot = q >> 4;
            int r4   = (q & 15) << 2;
            int s    = s0 + slot;
            float4 v = make_float4(0.f, 0.f, 0.f, 0.f);
            float  w = 0.f;
            int    t = -1;
            if (s < cnt) {
                t = g_tok[e * T_TOK + s];
                w = g_wt [e * T_TOK + s];
                v = *(const float4*)&g_S[(size_t)t * N_COLS + r4];
            }
            Hs[(r4 + 0) * HS_STRIDE + slot] = v.x * w;
            Hs[(r4 + 1) * HS_STRIDE + slot] = v.y * w;
            Hs[(r4 + 2) * HS_STRIDE + slot] = v.z * w;
            Hs[(r4 + 3) * HS_STRIDE + slot] = v.w * w;
            if (r4 == 0) stok[slot] = t;
        }
        __syncthreads();

        for (int d0 = 0; d0 < D_OUT; d0 += 128) {
            // ---- load B chunk (128 d x 64 r), transpose into [r][d] ----
#pragma unroll
            for (int it = 0; it < 8; it++) {
                int q  = tid + it * 256;
                int d  = q & 127;
                int r4 = (q >> 7) << 2;
                float4 v = *(const float4*)&Bm[((size_t)e * D_OUT + d0 + d) * R_RANK + r4];
                Bsh[(r4 + 0) * BS_STRIDE + d] = v.x;
                Bsh[(r4 + 1) * BS_STRIDE + d] = v.y;
                Bsh[(r4 + 2) * BS_STRIDE + d] = v.z;
                Bsh[(r4 + 3) * BS_STRIDE + d] = v.w;
            }
            __syncthreads();

            float acc[4][8];
#pragma unroll
            for (int i = 0; i < 4; i++)
#pragma unroll
                for (int j = 0; j < 8; j++) acc[i][j] = 0.f;

#pragma unroll
            for (int r = 0; r < 64; r++) {
                float4 av  = *(const float4*)&Hs[r * HS_STRIDE + a * 4];
                float4 bv0 = *(const float4*)&Bsh[r * BS_STRIDE + b * 8];
                float4 bv1 = *(const float4*)&Bsh[r * BS_STRIDE + b * 8 + 4];
                float aa[4] = {av.x, av.y, av.z, av.w};
                float bb[8] = {bv0.x, bv0.y, bv0.z, bv0.w, bv1.x, bv1.y, bv1.z, bv1.w};
#pragma unroll
                for (int i = 0; i < 4; i++)
#pragma unroll
                    for (int j = 0; j < 8; j++) acc[i][j] += aa[i] * bb[j];
            }

#pragma unroll
            for (int i = 0; i < 4; i++) {
                int t = stok[a * 4 + i];
                if (t < 0) continue;
                float* p = &out[(size_t)t * D_OUT + d0 + b * 8];
                red_v4(p,     acc[i][0], acc[i][1], acc[i][2], acc[i][3]);
                red_v4(p + 4, acc[i][4], acc[i][5], acc[i][6], acc[i][7]);
            }
            __syncthreads();
        }
        __syncthreads();
    }
}

// ============================================================================
// launch — fork {k1,k2} onto a side stream, overlapped with {k0,k3};
// join before k4. Event fork/join is graph-capture legal (branching graph).
// ============================================================================
extern "C" void kernel_launch(void* const* d_in, const int* in_sizes, int n_in,
                              void* d_out, int out_size)
{
    const float* x   = (const float*)d_in[0];
    const float* Wb  = (const float*)d_in[1];
    const float* bb  = (const float*)d_in[2];
    const float* A   = (const float*)d_in[3];
    const float* Bm  = (const float*)d_in[4];
    const float* Wr  = (const float*)d_in[5];
    const int* topk  = (n_in > 6) ? (const int*)d_in[6] : nullptr;
    float* out       = (float*)d_out;

    (void)in_sizes; (void)out_size;

    __half *p_xhi, *p_xlo, *p_whi;
    cudaGetSymbolAddress((void**)&p_xhi, g_xhi);
    cudaGetSymbolAddress((void**)&p_xlo, g_xlo);
    cudaGetSymbolAddress((void**)&p_whi, g_whi);

    static cudaStream_t s1 = nullptr;
    static cudaEvent_t  ev_fork = nullptr, ev_join = nullptr;
    static bool inited = false;
    if (!inited) {
        cudaStreamCreateWithFlags(&s1, cudaStreamNonBlocking);
        cudaEventCreateWithFlags(&ev_fork, cudaEventDisableTiming);
        cudaEventCreateWithFlags(&ev_join, cudaEventDisableTiming);
        cudaFuncSetAttribute(k3_mma_gemm, cudaFuncAttributeMaxDynamicSharedMemorySize, SMEM_DYN);
        cudaFuncSetAttribute(k4_delta,    cudaFuncAttributeMaxDynamicSharedMemorySize, K4_SMEM);
        inited = true;
    }

    int n4x = T_TOK * D_IN / 4, n4w = D_OUT * D_IN / 4;

    // fork side chain: k1 -> k2 on s1
    cudaEventRecord(ev_fork, 0);
    cudaStreamWaitEvent(s1, ev_fork, 0);
    k1_small_gemm<<<dim3(2, T_TOK / 128), 256, 0, s1>>>(x, A, Wr);
    k2_router   <<<T_TOK / 128, 128, 0, s1>>>(topk);
    cudaEventRecord(ev_join, s1);

    // main chain: converts + big GEMM
    k0_split_hl<<<(n4x + 255) / 256, 256>>>(x,  p_xhi, p_xlo, n4x);
    k0_split_h <<<(n4w + 255) / 256, 256>>>(Wb, p_whi, n4w);
    k3_mma_gemm<<<dim3(D_OUT / 128, T_TOK / 128), 256, SMEM_DYN>>>(bb, out);

    // join and run delta
    cudaStreamWaitEvent(0, ev_join, 0);
    k4_delta<<<N_EXP * 32, 256, K4_SMEM>>>(Bm, out);
}

// round 9
// speedup vs baseline: 3.0095x; 1.3244x over previous
#include <cuda_runtime.h>
#include <cuda_fp16.h>
#include <cstdint>

// Problem constants (fixed by setup_inputs)
#define T_TOK   8192      // B*S = 4*2048
#define D_IN    2048
#define D_OUT   2048
#define R_RANK  64
#define N_EXP   16
#define N_COLS  80        // R + E combined small-GEMM width

// ---------------- device scratch (no allocations allowed) ----------------
__device__ float g_S[T_TOK * N_COLS];        // [token][0..63]=res_hidden, [64..79]=router logits
__device__ int   g_cnt[N_EXP];
__device__ int   g_tok[N_EXP * T_TOK];
__device__ float g_wt [N_EXP * T_TOK];
// fp16 copies for the tensor-core base GEMM (single-term)
__device__ __half g_xh[T_TOK * D_IN];
__device__ __half g_wh[D_OUT * D_IN];

// ---------------- helpers ----------------
__device__ __forceinline__ uint32_t smem_u32(const void* p) {
    uint32_t a;
    asm("{ .reg .u64 t; cvta.to.shared.u64 t, %1; cvt.u32.u64 %0, t; }" : "=r"(a) : "l"(p));
    return a;
}
__device__ __forceinline__ void cp16(uint32_t s, const void* g) {
    asm volatile("cp.async.cg.shared.global [%0], [%1], 16;" :: "r"(s), "l"(g) : "memory");
}
__device__ __forceinline__ void ldmatrix_x4(uint32_t* r, uint32_t addr) {
    asm volatile("ldmatrix.sync.aligned.m8n8.x4.shared.b16 {%0,%1,%2,%3}, [%4];"
                 : "=r"(r[0]), "=r"(r[1]), "=r"(r[2]), "=r"(r[3]) : "r"(addr));
}
__device__ __forceinline__ void mma16816h(float* c, const uint32_t* a, uint32_t b0, uint32_t b1) {
    asm volatile(
        "mma.sync.aligned.m16n8k16.row.col.f32.f16.f16.f32 "
        "{%0,%1,%2,%3}, {%4,%5,%6,%7}, {%8,%9}, {%0,%1,%2,%3};"
        : "+f"(c[0]), "+f"(c[1]), "+f"(c[2]), "+f"(c[3])
        : "r"(a[0]), "r"(a[1]), "r"(a[2]), "r"(a[3]), "r"(b0), "r"(b1));
}
__device__ __forceinline__ void red_v4(float* p, float x, float y, float z, float w) {
    asm volatile("red.global.add.v4.f32 [%0], {%1,%2,%3,%4};"
                 :: "l"(p), "f"(x), "f"(y), "f"(z), "f"(w) : "memory");
}
#define CP_COMMIT() asm volatile("cp.async.commit_group;" ::: "memory")
#define CP_WAIT(n)  asm volatile("cp.async.wait_group %0;" :: "n"(n) : "memory")

// ============================================================================
// Kernel 0: fp32 -> fp16
// ============================================================================
__global__ __launch_bounds__(256) void k0_cvt(
    const float* __restrict__ src, __half* __restrict__ dst, int n4)
{
    int i = blockIdx.x * blockDim.x + threadIdx.x;
    if (i >= n4) return;
    float4 v = *(const float4*)&src[(size_t)i * 4];
    __half h[4];
    h[0] = __float2half_rn(v.x); h[1] = __float2half_rn(v.y);
    h[2] = __float2half_rn(v.z); h[3] = __float2half_rn(v.w);
    *(uint2*)&dst[(size_t)i * 4] = *(uint2*)h;
}

// ============================================================================
// Kernel 1: S = x @ [A^T | W_router^T]  (fp32 SIMT)
// ============================================================================
__global__ __launch_bounds__(256) void k1_small_gemm(
    const float* __restrict__ x,
    const float* __restrict__ A,
    const float* __restrict__ Wr)
{
    __shared__ float xs[128][68];
    __shared__ float ws[40][68];

    const int tid = threadIdx.x;
    if (blockIdx.x == 0 && blockIdx.y == 0 && tid < N_EXP) g_cnt[tid] = 0;

    const int m0 = blockIdx.y * 128;
    const int c0 = blockIdx.x * 40;
    const int tg = tid >> 3;
    const int cg = tid & 7;

    float acc[4][5];
#pragma unroll
    for (int i = 0; i < 4; i++)
#pragma unroll
        for (int j = 0; j < 5; j++) acc[i][j] = 0.f;

    for (int k0 = 0; k0 < D_IN; k0 += 64) {
#pragma unroll
        for (int it = 0; it < 8; it++) {
            int q = tid + it * 256;
            int row = q >> 4;
            int kc = (q & 15) << 2;
            float4 v = *(const float4*)&x[(size_t)(m0 + row) * D_IN + k0 + kc];
            *(float4*)&xs[row][kc] = v;
        }
        for (int q = tid; q < 40 * 16; q += 256) {
            int col = q >> 4;
            int kc = (q & 15) << 2;
            int gc = c0 + col;
            const float* src = (gc < R_RANK) ? (A + (size_t)gc * D_IN)
                                             : (Wr + (size_t)(gc - R_RANK) * D_IN);
            float4 v = *(const float4*)&src[k0 + kc];
            *(float4*)&ws[col][kc] = v;
        }
        __syncthreads();

#pragma unroll 16
        for (int kk = 0; kk < 64; kk++) {
            float av[4], bv[5];
#pragma unroll
            for (int i = 0; i < 4; i++) av[i] = xs[tg * 4 + i][kk];
#pragma unroll
            for (int j = 0; j < 5; j++) bv[j] = ws[cg * 5 + j][kk];
#pragma unroll
            for (int i = 0; i < 4; i++)
#pragma unroll
                for (int j = 0; j < 5; j++) acc[i][j] += av[i] * bv[j];
        }
        __syncthreads();
    }

#pragma unroll
    for (int i = 0; i < 4; i++) {
        size_t base = (size_t)(m0 + tg * 4 + i) * N_COLS + c0 + cg * 5;
#pragma unroll
        for (int j = 0; j < 5; j++) g_S[base + j] = acc[i][j];
    }
}

// ============================================================================
// Kernel 2: softmax + top-k + scatter
// ============================================================================
__global__ __launch_bounds__(128) void k2_router(const int* __restrict__ topk_ptr)
{
    int t = blockIdx.x * blockDim.x + threadIdx.x;
    if (t >= T_TOK) return;

    float p[N_EXP];
    float mx = -1e30f;
#pragma unroll
    for (int e = 0; e < N_EXP; e++) {
        p[e] = g_S[(size_t)t * N_COLS + R_RANK + e];
        mx = fmaxf(mx, p[e]);
    }
    float sum = 0.f;
#pragma unroll
    for (int e = 0; e < N_EXP; e++) { p[e] = __expf(p[e] - mx); sum += p[e]; }
    float inv = 1.f / sum;
#pragma unroll
    for (int e = 0; e < N_EXP; e++) p[e] *= inv;

    int k = topk_ptr ? *topk_ptr : 2;

    if (k > 0 && k < N_EXP) {
        unsigned sel = 0;
        float ssum = 0.f;
        for (int it = 0; it < k; it++) {
            int best = -1; float bv = -1.f;
#pragma unroll
            for (int e = 0; e < N_EXP; e++)
                if (!((sel >> e) & 1u) && p[e] > bv) { bv = p[e]; best = e; }
            sel |= 1u << best;
            ssum += bv;
        }
        float denom = 1.f / (ssum + 1e-6f);
#pragma unroll
        for (int e = 0; e < N_EXP; e++) {
            if ((sel >> e) & 1u) {
                float w = p[e] * denom;
                int slot = atomicAdd(&g_cnt[e], 1);
                g_tok[e * T_TOK + slot] = t;
                g_wt [e * T_TOK + slot] = w;
            }
        }
    } else {
#pragma unroll
        for (int e = 0; e < N_EXP; e++) {
            int slot = atomicAdd(&g_cnt[e], 1);
            g_tok[e * T_TOK + slot] = t;
            g_wt [e * T_TOK + slot] = p[e];
        }
    }
}

// ============================================================================
// Kernel 3: base GEMM via mma.sync fp16 (single term): out = xh @ wh^T + b
// CTA tile 128x128, BK=32, 8 warps (2x4), warp tile 64x32, 3-stage cp.async.
// ldmatrix.x4 fragment loads; smem row stride 80B -> conflict-free.
// ============================================================================
#define BK       32
#define NCHUNK   (D_IN / BK)                 // 64
#define MAT_BYTES (128 * 80)                 // 10240
#define STAGE_BYTES (2 * MAT_BYTES)          // 20480 (Ah | Bh)
#define SMEM_DYN (3 * STAGE_BYTES)           // 61440

__global__ __launch_bounds__(256, 2) void k3_mma_gemm(
    const float* __restrict__ bias, float* __restrict__ out)
{
    extern __shared__ char sm[];
    const int tid  = threadIdx.x;
    const int wid  = tid >> 5;
    const int lane = tid & 31;
    const int g    = lane >> 2;      // group id 0..7
    const int t4   = lane & 3;       // thread-in-group 0..3

    const int m0 = blockIdx.y * 128;
    const int n0 = blockIdx.x * 128;
    const int wm = (wid >> 2) * 64;  // warp M offset within CTA
    const int wn = (wid & 3) * 32;   // warp N offset within CTA

    const uint32_t sbase = smem_u32(sm);

    // ldmatrix per-lane address components
    const int a_row = ((lane >> 3) & 1) * 8 + (lane & 7);
    const int a_kb  = (lane >> 4) * 16;
    const int b_row = ((lane >> 4) & 1) * 8 + (lane & 7);
    const int b_kb  = ((lane >> 3) & 1) * 16;

    float acc[4][4][4];
#pragma unroll
    for (int mi = 0; mi < 4; mi++)
#pragma unroll
        for (int ni = 0; ni < 4; ni++)
#pragma unroll
            for (int r = 0; r < 4; r++) acc[mi][ni][r] = 0.f;

    // ---- async load of one k-chunk (Ah, Bh) into stage c%3 ----
    auto load_chunk = [&](int c) {
        const int p  = c % 3;
        const int k0 = c * BK;
#pragma unroll
        for (int it = 0; it < 4; it++) {
            int q    = tid + it * 256;          // 0..1023
            int mat  = q >> 9;                  // 0: Ah, 1: Bh
            int row  = (q >> 2) & 127;
            int quad = q & 3;
            const __half* src = mat ? g_wh : g_xh;
            int grow = (mat ? n0 : m0) + row;
            uint32_t saddr = sbase + p * STAGE_BYTES + mat * MAT_BYTES
                           + row * 80 + quad * 16;
            cp16(saddr, &src[(size_t)grow * D_IN + k0 + quad * 8]);
        }
        CP_COMMIT();
    };

    load_chunk(0);
    load_chunk(1);

    for (int c = 0; c < NCHUNK; c++) {
        if (c + 2 < NCHUNK) { load_chunk(c + 2); CP_WAIT(2); }
        else if (c + 1 < NCHUNK) { CP_WAIT(1); }
        else { CP_WAIT(0); }
        __syncthreads();

        const uint32_t stg = sbase + (c % 3) * STAGE_BYTES;
        const uint32_t sAh = stg;
        const uint32_t sBh = stg + MAT_BYTES;

#pragma unroll
        for (int ks = 0; ks < 2; ks++) {
            const uint32_t kso = ks * 32;

            uint32_t aH[4][4];
#pragma unroll
            for (int mi = 0; mi < 4; mi++) {
                uint32_t aoff = (uint32_t)((wm + mi * 16 + a_row) * 80) + kso + a_kb;
                ldmatrix_x4(aH[mi], sAh + aoff);
            }
            uint32_t bH[4][2];
#pragma unroll
            for (int nj = 0; nj < 2; nj++) {
                uint32_t boff = (uint32_t)((wn + nj * 16 + b_row) * 80) + kso + b_kb;
                uint32_t th[4];
                ldmatrix_x4(th, sBh + boff);
                bH[nj * 2][0] = th[0]; bH[nj * 2][1] = th[1];
                bH[nj * 2 + 1][0] = th[2]; bH[nj * 2 + 1][1] = th[3];
            }

#pragma unroll
            for (int ni = 0; ni < 4; ni++)
#pragma unroll
                for (int mi = 0; mi < 4; mi++)
                    mma16816h(acc[mi][ni], aH[mi], bH[ni][0], bH[ni][1]);
        }
        __syncthreads();
    }

    // ---- epilogue: bias add + store ----
#pragma unroll
    for (int mi = 0; mi < 4; mi++) {
        int row = m0 + wm + mi * 16 + g;
#pragma unroll
        for (int ni = 0; ni < 4; ni++) {
            int col = n0 + wn + ni * 8 + t4 * 2;
            float2 bv = *(const float2*)&bias[col];
            float2 o0, o1;
            o0.x = acc[mi][ni][0] + bv.x;
            o0.y = acc[mi][ni][1] + bv.y;
            o1.x = acc[mi][ni][2] + bv.x;
            o1.y = acc[mi][ni][3] + bv.y;
            *(float2*)&out[(size_t)row * D_OUT + col]       = o0;
            *(float2*)&out[(size_t)(row + 8) * D_OUT + col] = o1;
        }
    }
}

// ============================================================================
// Kernel 4: delta — expert-grouped, block = (expert, 64-token tile), d-loop
// inside (H loaded once). 4 tok x 8 d microtile. red.v4 accumulation.
// ============================================================================
#define HS_STRIDE  68
#define BS_STRIDE  132
#define K4_SMEM    (64 * HS_STRIDE * 4 + 64 * BS_STRIDE * 4 + 64 * 4)  // 51968

__global__ __launch_bounds__(256) void k4_delta(
    const float* __restrict__ Bm,
    float* __restrict__ out)
{
    extern __shared__ float sm4[];
    float* Hs  = sm4;                          // [64][HS_STRIDE]  (r-major, w-scaled)
    float* Bsh = sm4 + 64 * HS_STRIDE;         // [64][BS_STRIDE]  (r-major)
    int*   stok = (int*)(sm4 + 64 * HS_STRIDE + 64 * BS_STRIDE);

    const int e     = blockIdx.x >> 5;         // 16 experts
    const int stile = blockIdx.x & 31;         // 32 token tiles
    const int cnt   = g_cnt[e];
    const int tid   = threadIdx.x;

    if (stile * 64 >= cnt) return;

    const int a = tid >> 4;    // 0..15 token group (4 tokens)
    const int b = tid & 15;    // 0..15 d group (8 d)

    for (int s0 = stile * 64; s0 < cnt; s0 += 32 * 64) {
        // ---- load H tile (64 slots x 64 r), transpose, scale by weight ----
#pragma unroll
        for (int it = 0; it < 4; it++) {
            int q    = tid + it * 256;
            int slot = q >> 4;
            int r4   = (q & 15) << 2;
            int s    = s0 + slot;
            float4 v = make_float4(0.f, 0.f, 0.f, 0.f);
            float  w = 0.f;
            int    t = -1;
            if (s < cnt) {
                t = g_tok[e * T_TOK + s];
                w = g_wt [e * T_TOK + s];
                v = *(const float4*)&g_S[(size_t)t * N_COLS + r4];
            }
            Hs[(r4 + 0) * HS_STRIDE + slot] = v.x * w;
            Hs[(r4 + 1) * HS_STRIDE + slot] = v.y * w;
            Hs[(r4 + 2) * HS_STRIDE + slot] = v.z * w;
            Hs[(r4 + 3) * HS_STRIDE + slot] = v.w * w;
            if (r4 == 0) stok[slot] = t;
        }
        __syncthreads();

        for (int d0 = 0; d0 < D_OUT; d0 += 128) {
            // ---- load B chunk (128 d x 64 r), transpose into [r][d] ----
#pragma unroll
            for (int it = 0; it < 8; it++) {
                int q  = tid + it * 256;
                int d  = q & 127;
                int r4 = (q >> 7) << 2;
                float4 v = *(const float4*)&Bm[((size_t)e * D_OUT + d0 + d) * R_RANK + r4];
                Bsh[(r4 + 0) * BS_STRIDE + d] = v.x;
                Bsh[(r4 + 1) * BS_STRIDE + d] = v.y;
                Bsh[(r4 + 2) * BS_STRIDE + d] = v.z;
                Bsh[(r4 + 3) * BS_STRIDE + d] = v.w;
            }
            __syncthreads();

            float acc[4][8];
#pragma unroll
            for (int i = 0; i < 4; i++)
#pragma unroll
                for (int j = 0; j < 8; j++) acc[i][j] = 0.f;

#pragma unroll
            for (int r = 0; r < 64; r++) {
                float4 av  = *(const float4*)&Hs[r * HS_STRIDE + a * 4];
                float4 bv0 = *(const float4*)&Bsh[r * BS_STRIDE + b * 8];
                float4 bv1 = *(const float4*)&Bsh[r * BS_STRIDE + b * 8 + 4];
                float aa[4] = {av.x, av.y, av.z, av.w};
                float bb[8] = {bv0.x, bv0.y, bv0.z, bv0.w, bv1.x, bv1.y, bv1.z, bv1.w};
#pragma unroll
                for (int i = 0; i < 4; i++)
#pragma unroll
                    for (int j = 0; j < 8; j++) acc[i][j] += aa[i] * bb[j];
            }

#pragma unroll
            for (int i = 0; i < 4; i++) {
                int t = stok[a * 4 + i];
                if (t < 0) continue;
                float* p = &out[(size_t)t * D_OUT + d0 + b * 8];
                red_v4(p,     acc[i][0], acc[i][1], acc[i][2], acc[i][3]);
                red_v4(p + 4, acc[i][4], acc[i][5], acc[i][6], acc[i][7]);
            }
            __syncthreads();
        }
        __syncthreads();
    }
}

// ============================================================================
// launch — fork {k1,k2} onto a side stream, overlapped with {k0,k3};
// join before k4.
// ============================================================================
extern "C" void kernel_launch(void* const* d_in, const int* in_sizes, int n_in,
                              void* d_out, int out_size)
{
    const float* x   = (const float*)d_in[0];
    const float* Wb  = (const float*)d_in[1];
    const float* bb  = (const float*)d_in[2];
    const float* A   = (const float*)d_in[3];
    const float* Bm  = (const float*)d_in[4];
    const float* Wr  = (const float*)d_in[5];
    const int* topk  = (n_in > 6) ? (const int*)d_in[6] : nullptr;
    float* out       = (float*)d_out;

    (void)in_sizes; (void)out_size;

    __half *p_xh, *p_wh;
    cudaGetSymbolAddress((void**)&p_xh, g_xh);
    cudaGetSymbolAddress((void**)&p_wh, g_wh);

    static cudaStream_t s1 = nullptr;
    static cudaEvent_t  ev_fork = nullptr, ev_join = nullptr;
    static bool inited = false;
    if (!inited) {
        cudaStreamCreateWithFlags(&s1, cudaStreamNonBlocking);
        cudaEventCreateWithFlags(&ev_fork, cudaEventDisableTiming);
        cudaEventCreateWithFlags(&ev_join, cudaEventDisableTiming);
        cudaFuncSetAttribute(k3_mma_gemm, cudaFuncAttributeMaxDynamicSharedMemorySize, SMEM_DYN);
        cudaFuncSetAttribute(k4_delta,    cudaFuncAttributeMaxDynamicSharedMemorySize, K4_SMEM);
        inited = true;
    }

    int n4x = T_TOK * D_IN / 4, n4w = D_OUT * D_IN / 4;

    // fork side chain: k1 -> k2 on s1
    cudaEventRecord(ev_fork, 0);
    cudaStreamWaitEvent(s1, ev_fork, 0);
    k1_small_gemm<<<dim3(2, T_TOK / 128), 256, 0, s1>>>(x, A, Wr);
    k2_router   <<<T_TOK / 128, 128, 0, s1>>>(topk);
    cudaEventRecord(ev_join, s1);

    // main chain: converts + big GEMM
    k0_cvt<<<(n4x + 255) / 256, 256>>>(x,  p_xh, n4x);
    k0_cvt<<<(n4w + 255) / 256, 256>>>(Wb, p_wh, n4w);
    k3_mma_gemm<<<dim3(D_OUT / 128, T_TOK / 128), 256, SMEM_DYN>>>(bb, out);

    // join and run delta
    cudaStreamWaitEvent(0, ev_join, 0);
    k4_delta<<<N_EXP * 32, 256, K4_SMEM>>>(Bm, out);
}

// round 10
// speedup vs baseline: 4.6748x; 1.5534x over previous
#include <cuda_runtime.h>
#include <cuda_fp16.h>
#include <cstdint>

// Problem constants (fixed by setup_inputs)
#define T_TOK   8192      // B*S = 4*2048
#define D_IN    2048
#define D_OUT   2048
#define R_RANK  64
#define N_EXP   16
#define N_COLS  80        // R + E combined small-GEMM width

// ---------------- device scratch (no allocations allowed) ----------------
__device__ float g_S[T_TOK * N_COLS];        // [token][0..63]=res_hidden, [64..79]=router logits
__device__ int   g_cnt[N_EXP];
__device__ int   g_tok[N_EXP * T_TOK];
__device__ float g_wt [N_EXP * T_TOK];
// fp16 copies for the tensor-core GEMMs
__device__ __half g_xh[T_TOK * D_IN];
__device__ __half g_wh[D_OUT * D_IN];
__device__ __half g_bh[N_EXP * D_OUT * R_RANK];

// ---------------- helpers ----------------
__device__ __forceinline__ uint32_t smem_u32(const void* p) {
    uint32_t a;
    asm("{ .reg .u64 t; cvta.to.shared.u64 t, %1; cvt.u32.u64 %0, t; }" : "=r"(a) : "l"(p));
    return a;
}
__device__ __forceinline__ void cp16(uint32_t s, const void* g) {
    asm volatile("cp.async.cg.shared.global [%0], [%1], 16;" :: "r"(s), "l"(g) : "memory");
}
__device__ __forceinline__ void ldmatrix_x4(uint32_t* r, uint32_t addr) {
    asm volatile("ldmatrix.sync.aligned.m8n8.x4.shared.b16 {%0,%1,%2,%3}, [%4];"
                 : "=r"(r[0]), "=r"(r[1]), "=r"(r[2]), "=r"(r[3]) : "r"(addr));
}
__device__ __forceinline__ void mma16816h(float* c, const uint32_t* a, uint32_t b0, uint32_t b1) {
    asm volatile(
        "mma.sync.aligned.m16n8k16.row.col.f32.f16.f16.f32 "
        "{%0,%1,%2,%3}, {%4,%5,%6,%7}, {%8,%9}, {%0,%1,%2,%3};"
        : "+f"(c[0]), "+f"(c[1]), "+f"(c[2]), "+f"(c[3])
        : "r"(a[0]), "r"(a[1]), "r"(a[2]), "r"(a[3]), "r"(b0), "r"(b1));
}
__device__ __forceinline__ void red_v2(float* p, float x, float y) {
    asm volatile("red.global.add.v2.f32 [%0], {%1,%2};"
                 :: "l"(p), "f"(x), "f"(y) : "memory");
}
#define CP_COMMIT() asm volatile("cp.async.commit_group;" ::: "memory")
#define CP_WAIT(n)  asm volatile("cp.async.wait_group %0;" :: "n"(n) : "memory")

// ============================================================================
// Kernel 0: fp32 -> fp16
// ============================================================================
__global__ __launch_bounds__(256) void k0_cvt(
    const float* __restrict__ src, __half* __restrict__ dst, int n4)
{
    int i = blockIdx.x * blockDim.x + threadIdx.x;
    if (i >= n4) return;
    float4 v = *(const float4*)&src[(size_t)i * 4];
    __half h[4];
    h[0] = __float2half_rn(v.x); h[1] = __float2half_rn(v.y);
    h[2] = __float2half_rn(v.z); h[3] = __float2half_rn(v.w);
    *(uint2*)&dst[(size_t)i * 4] = *(uint2*)h;
}

// ============================================================================
// Kernel 1: S = x @ [A^T | W_router^T]  (fp32 SIMT)
// ============================================================================
__global__ __launch_bounds__(256) void k1_small_gemm(
    const float* __restrict__ x,
    const float* __restrict__ A,
    const float* __restrict__ Wr)
{
    __shared__ float xs[128][68];
    __shared__ float ws[40][68];

    const int tid = threadIdx.x;
    if (blockIdx.x == 0 && blockIdx.y == 0 && tid < N_EXP) g_cnt[tid] = 0;

    const int m0 = blockIdx.y * 128;
    const int c0 = blockIdx.x * 40;
    const int tg = tid >> 3;
    const int cg = tid & 7;

    float acc[4][5];
#pragma unroll
    for (int i = 0; i < 4; i++)
#pragma unroll
        for (int j = 0; j < 5; j++) acc[i][j] = 0.f;

    for (int k0 = 0; k0 < D_IN; k0 += 64) {
#pragma unroll
        for (int it = 0; it < 8; it++) {
            int q = tid + it * 256;
            int row = q >> 4;
            int kc = (q & 15) << 2;
            float4 v = *(const float4*)&x[(size_t)(m0 + row) * D_IN + k0 + kc];
            *(float4*)&xs[row][kc] = v;
        }
        for (int q = tid; q < 40 * 16; q += 256) {
            int col = q >> 4;
            int kc = (q & 15) << 2;
            int gc = c0 + col;
            const float* src = (gc < R_RANK) ? (A + (size_t)gc * D_IN)
                                             : (Wr + (size_t)(gc - R_RANK) * D_IN);
            float4 v = *(const float4*)&src[k0 + kc];
            *(float4*)&ws[col][kc] = v;
        }
        __syncthreads();

#pragma unroll 16
        for (int kk = 0; kk < 64; kk++) {
            float av[4], bv[5];
#pragma unroll
            for (int i = 0; i < 4; i++) av[i] = xs[tg * 4 + i][kk];
#pragma unroll
            for (int j = 0; j < 5; j++) bv[j] = ws[cg * 5 + j][kk];
#pragma unroll
            for (int i = 0; i < 4; i++)
#pragma unroll
                for (int j = 0; j < 5; j++) acc[i][j] += av[i] * bv[j];
        }
        __syncthreads();
    }

#pragma unroll
    for (int i = 0; i < 4; i++) {
        size_t base = (size_t)(m0 + tg * 4 + i) * N_COLS + c0 + cg * 5;
#pragma unroll
        for (int j = 0; j < 5; j++) g_S[base + j] = acc[i][j];
    }
}

// ============================================================================
// Kernel 2: softmax + top-k + scatter
// ============================================================================
__global__ __launch_bounds__(128) void k2_router(const int* __restrict__ topk_ptr)
{
    int t = blockIdx.x * blockDim.x + threadIdx.x;
    if (t >= T_TOK) return;

    float p[N_EXP];
    float mx = -1e30f;
#pragma unroll
    for (int e = 0; e < N_EXP; e++) {
        p[e] = g_S[(size_t)t * N_COLS + R_RANK + e];
        mx = fmaxf(mx, p[e]);
    }
    float sum = 0.f;
#pragma unroll
    for (int e = 0; e < N_EXP; e++) { p[e] = __expf(p[e] - mx); sum += p[e]; }
    float inv = 1.f / sum;
#pragma unroll
    for (int e = 0; e < N_EXP; e++) p[e] *= inv;

    int k = topk_ptr ? *topk_ptr : 2;

    if (k > 0 && k < N_EXP) {
        unsigned sel = 0;
        float ssum = 0.f;
        for (int it = 0; it < k; it++) {
            int best = -1; float bv = -1.f;
#pragma unroll
            for (int e = 0; e < N_EXP; e++)
                if (!((sel >> e) & 1u) && p[e] > bv) { bv = p[e]; best = e; }
            sel |= 1u << best;
            ssum += bv;
        }
        float denom = 1.f / (ssum + 1e-6f);
#pragma unroll
        for (int e = 0; e < N_EXP; e++) {
            if ((sel >> e) & 1u) {
                float w = p[e] * denom;
                int slot = atomicAdd(&g_cnt[e], 1);
                g_tok[e * T_TOK + slot] = t;
                g_wt [e * T_TOK + slot] = w;
            }
        }
    } else {
#pragma unroll
        for (int e = 0; e < N_EXP; e++) {
            int slot = atomicAdd(&g_cnt[e], 1);
            g_tok[e * T_TOK + slot] = t;
            g_wt [e * T_TOK + slot] = p[e];
        }
    }
}

// ============================================================================
// Kernel 3: base GEMM via mma.sync fp16 (single term): out = xh @ wh^T + b
// CTA tile 128x128, BK=32, 8 warps (2x4), warp tile 64x32, 3-stage cp.async.
// ============================================================================
#define BK       32
#define NCHUNK   (D_IN / BK)                 // 64
#define MAT_BYTES (128 * 80)                 // 10240
#define STAGE_BYTES (2 * MAT_BYTES)          // 20480 (Ah | Bh)
#define SMEM_DYN (3 * STAGE_BYTES)           // 61440

__global__ __launch_bounds__(256, 2) void k3_mma_gemm(
    const float* __restrict__ bias, float* __restrict__ out)
{
    extern __shared__ char sm[];
    const int tid  = threadIdx.x;
    const int wid  = tid >> 5;
    const int lane = tid & 31;
    const int g    = lane >> 2;      // group id 0..7
    const int t4   = lane & 3;       // thread-in-group 0..3

    const int m0 = blockIdx.y * 128;
    const int n0 = blockIdx.x * 128;
    const int wm = (wid >> 2) * 64;  // warp M offset within CTA
    const int wn = (wid & 3) * 32;   // warp N offset within CTA

    const uint32_t sbase = smem_u32(sm);

    const int a_row = ((lane >> 3) & 1) * 8 + (lane & 7);
    const int a_kb  = (lane >> 4) * 16;
    const int b_row = ((lane >> 4) & 1) * 8 + (lane & 7);
    const int b_kb  = ((lane >> 3) & 1) * 16;

    float acc[4][4][4];
#pragma unroll
    for (int mi = 0; mi < 4; mi++)
#pragma unroll
        for (int ni = 0; ni < 4; ni++)
#pragma unroll
            for (int r = 0; r < 4; r++) acc[mi][ni][r] = 0.f;

    auto load_chunk = [&](int c) {
        const int p  = c % 3;
        const int k0 = c * BK;
#pragma unroll
        for (int it = 0; it < 4; it++) {
            int q    = tid + it * 256;          // 0..1023
            int mat  = q >> 9;                  // 0: Ah, 1: Bh
            int row  = (q >> 2) & 127;
            int quad = q & 3;
            const __half* src = mat ? g_wh : g_xh;
            int grow = (mat ? n0 : m0) + row;
            uint32_t saddr = sbase + p * STAGE_BYTES + mat * MAT_BYTES
                           + row * 80 + quad * 16;
            cp16(saddr, &src[(size_t)grow * D_IN + k0 + quad * 8]);
        }
        CP_COMMIT();
    };

    load_chunk(0);
    load_chunk(1);

    for (int c = 0; c < NCHUNK; c++) {
        if (c + 2 < NCHUNK) { load_chunk(c + 2); CP_WAIT(2); }
        else if (c + 1 < NCHUNK) { CP_WAIT(1); }
        else { CP_WAIT(0); }
        __syncthreads();

        const uint32_t stg = sbase + (c % 3) * STAGE_BYTES;
        const uint32_t sAh = stg;
        const uint32_t sBh = stg + MAT_BYTES;

#pragma unroll
        for (int ks = 0; ks < 2; ks++) {
            const uint32_t kso = ks * 32;

            uint32_t aH[4][4];
#pragma unroll
            for (int mi = 0; mi < 4; mi++) {
                uint32_t aoff = (uint32_t)((wm + mi * 16 + a_row) * 80) + kso + a_kb;
                ldmatrix_x4(aH[mi], sAh + aoff);
            }
            uint32_t bH[4][2];
#pragma unroll
            for (int nj = 0; nj < 2; nj++) {
                uint32_t boff = (uint32_t)((wn + nj * 16 + b_row) * 80) + kso + b_kb;
                uint32_t th[4];
                ldmatrix_x4(th, sBh + boff);
                bH[nj * 2][0] = th[0]; bH[nj * 2][1] = th[1];
                bH[nj * 2 + 1][0] = th[2]; bH[nj * 2 + 1][1] = th[3];
            }

#pragma unroll
            for (int ni = 0; ni < 4; ni++)
#pragma unroll
                for (int mi = 0; mi < 4; mi++)
                    mma16816h(acc[mi][ni], aH[mi], bH[ni][0], bH[ni][1]);
        }
        __syncthreads();
    }

#pragma unroll
    for (int mi = 0; mi < 4; mi++) {
        int row = m0 + wm + mi * 16 + g;
#pragma unroll
        for (int ni = 0; ni < 4; ni++) {
            int col = n0 + wn + ni * 8 + t4 * 2;
            float2 bv = *(const float2*)&bias[col];
            float2 o0, o1;
            o0.x = acc[mi][ni][0] + bv.x;
            o0.y = acc[mi][ni][1] + bv.y;
            o1.x = acc[mi][ni][2] + bv.x;
            o1.y = acc[mi][ni][3] + bv.y;
            *(float2*)&out[(size_t)row * D_OUT + col]       = o0;
            *(float2*)&out[(size_t)(row + 8) * D_OUT + col] = o1;
        }
    }
}

// ============================================================================
// Kernel 4: delta via fp16 mma.sync.
// Block = (expert, 64-slot tile). H (64 slots x 64 r) weighted fp16 in smem;
// B chunks (128 d x 64 r) fp16 double-buffered cp.async. 8 warps: warp tile
// 16 slots x 64 d. Epilogue: red.global.add.v2.f32 into out.
// ============================================================================
#define K4_STR     144                       // smem row stride (128B data + 16 pad)
#define K4_H_BYTES (64 * K4_STR)             // 9216
#define K4_B_BYTES (128 * K4_STR)            // 18432
#define K4_SMEM    (K4_H_BYTES + 2 * K4_B_BYTES + 256)   // 46336

__global__ __launch_bounds__(256) void k4_delta(
    const __half* __restrict__ Bh, float* __restrict__ out)
{
    extern __shared__ char sm4[];
    const uint32_t sbase = smem_u32(sm4);
    const uint32_t sH = sbase;
    const uint32_t sB = sbase + K4_H_BYTES;
    int* stok = (int*)(sm4 + K4_H_BYTES + 2 * K4_B_BYTES);

    const int e     = blockIdx.x >> 5;       // 16 experts
    const int stile = blockIdx.x & 31;       // 32 slot tiles
    const int cnt   = g_cnt[e];
    const int tid   = threadIdx.x;
    const int wid   = tid >> 5;
    const int lane  = tid & 31;
    const int g     = lane >> 2;
    const int t4    = lane & 3;
    const int sg    = wid & 3;               // slot group (16 slots)
    const int dg    = wid >> 2;              // d group (64 d)

    if (stile * 64 >= cnt) return;

    const int a_row = ((lane >> 3) & 1) * 8 + (lane & 7);
    const int a_kb  = (lane >> 4) * 16;
    const int b_row = ((lane >> 4) & 1) * 8 + (lane & 7);
    const int b_kb  = ((lane >> 3) & 1) * 16;

    const __half* Be = Bh + (size_t)e * D_OUT * R_RANK;

    for (int s0 = stile * 64; s0 < cnt; s0 += 32 * 64) {
        // ---- load H tile: 64 slots x 64 r, weight-scaled, fp16 ----
        {
            int slot = tid >> 2;
            int rq   = (tid & 3) * 16;
            int s    = s0 + slot;
            float w = 0.f; int t = -1;
            float vv[16];
#pragma unroll
            for (int j = 0; j < 16; j++) vv[j] = 0.f;
            if (s < cnt) {
                t = g_tok[e * T_TOK + s];
                w = g_wt [e * T_TOK + s];
                const float4* hp = (const float4*)&g_S[(size_t)t * N_COLS + rq];
#pragma unroll
                for (int j = 0; j < 4; j++) *(float4*)&vv[j * 4] = hp[j];
            }
            __half hh[16];
#pragma unroll
            for (int j = 0; j < 16; j++) hh[j] = __float2half_rn(vv[j] * w);
            char* hp = sm4 + slot * K4_STR + rq * 2;
            *(uint4*)hp       = *(uint4*)&hh[0];
            *(uint4*)(hp + 16) = *(uint4*)&hh[8];
            if (rq == 0) stok[slot] = t;
        }

        // ---- B chunk pipeline over d0 (16 chunks of 128 d) ----
        auto loadB = [&](int i) {
            uint32_t dst = sB + (i & 1) * K4_B_BYTES;
            int d0 = i * 128;
#pragma unroll
            for (int it = 0; it < 4; it++) {
                int q   = tid + it * 256;      // 0..1023
                int row = q >> 3;
                int cb  = (q & 7) * 16;        // byte offset within 128B row
                cp16(dst + row * K4_STR + cb,
                     (const char*)&Be[(size_t)(d0 + row) * R_RANK] + cb);
            }
            CP_COMMIT();
        };

        loadB(0);
        __syncthreads();   // H + stok visible

        for (int i = 0; i < 16; i++) {
            if (i + 1 < 16) { loadB(i + 1); CP_WAIT(1); }
            else { CP_WAIT(0); }
            __syncthreads();

            const uint32_t stg = sB + (i & 1) * K4_B_BYTES;

            float acc[8][4];
#pragma unroll
            for (int ni = 0; ni < 8; ni++)
#pragma unroll
                for (int r = 0; r < 4; r++) acc[ni][r] = 0.f;

#pragma unroll
            for (int ks = 0; ks < 4; ks++) {
                uint32_t a[4];
                ldmatrix_x4(a, sH + (uint32_t)((sg * 16 + a_row) * K4_STR) + ks * 32 + a_kb);
#pragma unroll
                for (int nj = 0; nj < 4; nj++) {
                    uint32_t bf[4];
                    ldmatrix_x4(bf, stg + (uint32_t)((dg * 64 + nj * 16 + b_row) * K4_STR)
                                     + ks * 32 + b_kb);
                    mma16816h(acc[nj * 2],     a, bf[0], bf[1]);
                    mma16816h(acc[nj * 2 + 1], a, bf[2], bf[3]);
                }
            }

            // ---- epilogue: red.v2 into out ----
            int t0 = stok[sg * 16 + g];
            int t1 = stok[sg * 16 + g + 8];
            int d0 = i * 128;
#pragma unroll
            for (int ni = 0; ni < 8; ni++) {
                int col = d0 + dg * 64 + ni * 8 + t4 * 2;
                if (t0 >= 0) red_v2(&out[(size_t)t0 * D_OUT + col], acc[ni][0], acc[ni][1]);
                if (t1 >= 0) red_v2(&out[(size_t)t1 * D_OUT + col], acc[ni][2], acc[ni][3]);
            }
            __syncthreads();   // stage i&1 free for reuse at i+2
        }
    }
}

// ============================================================================
// launch — fork {k1,k2,Bm-convert} onto side stream, overlapped with {k0,k3};
// join before k4.
// ============================================================================
extern "C" void kernel_launch(void* const* d_in, const int* in_sizes, int n_in,
                              void* d_out, int out_size)
{
    const float* x   = (const float*)d_in[0];
    const float* Wb  = (const float*)d_in[1];
    const float* bb  = (const float*)d_in[2];
    const float* A   = (const float*)d_in[3];
    const float* Bm  = (const float*)d_in[4];
    const float* Wr  = (const float*)d_in[5];
    const int* topk  = (n_in > 6) ? (const int*)d_in[6] : nullptr;
    float* out       = (float*)d_out;

    (void)in_sizes; (void)out_size;

    __half *p_xh, *p_wh, *p_bh;
    cudaGetSymbolAddress((void**)&p_xh, g_xh);
    cudaGetSymbolAddress((void**)&p_wh, g_wh);
    cudaGetSymbolAddress((void**)&p_bh, g_bh);

    static cudaStream_t s1 = nullptr;
    static cudaEvent_t  ev_fork = nullptr, ev_join = nullptr;
    static bool inited = false;
    if (!inited) {
        cudaStreamCreateWithFlags(&s1, cudaStreamNonBlocking);
        cudaEventCreateWithFlags(&ev_fork, cudaEventDisableTiming);
        cudaEventCreateWithFlags(&ev_join, cudaEventDisableTiming);
        cudaFuncSetAttribute(k3_mma_gemm, cudaFuncAttributeMaxDynamicSharedMemorySize, SMEM_DYN);
        cudaFuncSetAttribute(k4_delta,    cudaFuncAttributeMaxDynamicSharedMemorySize, K4_SMEM);
        inited = true;
    }

    int n4x = T_TOK * D_IN / 4, n4w = D_OUT * D_IN / 4;
    int n4b = N_EXP * D_OUT * R_RANK / 4;

    // fork side chain: k1 -> k2 -> B convert on s1
    cudaEventRecord(ev_fork, 0);
    cudaStreamWaitEvent(s1, ev_fork, 0);
    k1_small_gemm<<<dim3(2, T_TOK / 128), 256, 0, s1>>>(x, A, Wr);
    k2_router   <<<T_TOK / 128, 128, 0, s1>>>(topk);
    k0_cvt      <<<(n4b + 255) / 256, 256, 0, s1>>>(Bm, p_bh, n4b);
    cudaEventRecord(ev_join, s1);

    // main chain: converts + big GEMM
    k0_cvt<<<(n4x + 255) / 256, 256>>>(x,  p_xh, n4x);
    k0_cvt<<<(n4w + 255) / 256, 256>>>(Wb, p_wh, n4w);
    k3_mma_gemm<<<dim3(D_OUT / 128, T_TOK / 128), 256, SMEM_DYN>>>(bb, out);

    // join and run delta
    cudaStreamWaitEvent(0, ev_join, 0);
    k4_delta<<<N_EXP * 32, 256, K4_SMEM>>>(p_bh, out);
}